// round 11
// baseline (speedup 1.0000x reference)
#include <cuda_runtime.h>
#include <cuda_bf16.h>
#include <cstdint>
#include <cstddef>

#define D_IN   128
#define D_OUT  128
#define D_EDGE 32
#define MAX_NODES 100000

__device__ float g_xwu[(size_t)MAX_NODES * D_OUT];
__device__ float g_xwi[(size_t)MAX_NODES * D_OUT];

// ============================= common helpers ==============================
__device__ __forceinline__ uint32_t smem_u32(const void* p) {
    uint32_t a;
    asm("{ .reg .u64 t; cvta.to.shared.u64 t, %1; cvt.u32.u64 %0, t; }"
        : "=r"(a) : "l"(p));
    return a;
}
__device__ __forceinline__ uint32_t bf2bits(__nv_bfloat162 h) {
    return *reinterpret_cast<uint32_t*>(&h);
}
__device__ __forceinline__ void cvt_hi_lo(float4 x, uint2& hi, uint2& lo) {
    __nv_bfloat162 h01 = __floats2bfloat162_rn(x.x, x.y);
    __nv_bfloat162 h23 = __floats2bfloat162_rn(x.z, x.w);
    float2 f01 = __bfloat1622float2(h01);
    float2 f23 = __bfloat1622float2(h23);
    __nv_bfloat162 l01 = __floats2bfloat162_rn(x.x - f01.x, x.y - f01.y);
    __nv_bfloat162 l23 = __floats2bfloat162_rn(x.z - f23.x, x.w - f23.y);
    hi = make_uint2(bf2bits(h01), bf2bits(h23));
    lo = make_uint2(bf2bits(l01), bf2bits(l23));
}

#define LDSM4(r, addr) \
    asm volatile("ldmatrix.sync.aligned.m8n8.x4.shared.b16 {%0,%1,%2,%3}, [%4];" \
        : "=r"((r)[0]), "=r"((r)[1]), "=r"((r)[2]), "=r"((r)[3]) : "r"(addr))
#define LDSM4T(r, addr) \
    asm volatile("ldmatrix.sync.aligned.m8n8.x4.trans.shared.b16 {%0,%1,%2,%3}, [%4];" \
        : "=r"((r)[0]), "=r"((r)[1]), "=r"((r)[2]), "=r"((r)[3]) : "r"(addr))
#define MMA16816(c, a, b0_, b1_) \
    asm volatile("mma.sync.aligned.m16n8k16.row.col.f32.bf16.bf16.f32 " \
        "{%0,%1,%2,%3}, {%4,%5,%6,%7}, {%8,%9}, {%0,%1,%2,%3};" \
        : "+f"((c)[0]), "+f"((c)[1]), "+f"((c)[2]), "+f"((c)[3]) \
        : "r"((a)[0]), "r"((a)[1]), "r"((a)[2]), "r"((a)[3]), "r"(b0_), "r"(b1_))

#define CPA16(s, g, sz) \
    asm volatile("cp.async.cg.shared.global [%0], [%1], 16, %2;" \
                 :: "r"(s), "l"(g), "r"(sz) : "memory")
#define CPA_COMMIT() asm volatile("cp.async.commit_group;" ::: "memory")
#define CPA_WAIT0()  asm volatile("cp.async.wait_group 0;" ::: "memory")

#define RED_V2(p, a, b) \
    asm volatile("red.global.add.v2.f32 [%0], {%1,%2};" \
                 :: "l"(p), "f"(a), "f"(b) : "memory")

// ---------------------------------------------------------------------------
// Node stage (R10, unchanged): tensor-core + cp.async pipelined, 4 fused GEMMs.
// ---------------------------------------------------------------------------
#define NT_THREADS 512
#define XSTRIDE    272
#define NXHI 0
#define NXLO 34816
#define NWHI 69632
#define NWLO 104448
#define NRAW 139264
#define NBS  204800
#define NT_SMEM (NBS + 512)

__global__ __launch_bounds__(NT_THREADS, 1)
void node_tc_kernel(const float* __restrict__ Xu, const float* __restrict__ Xi,
                    const float* __restrict__ Wsu, const float* __restrict__ bu,
                    float* __restrict__ xwu,
                    const float* __restrict__ Wlu, const float* __restrict__ blu,
                    float* __restrict__ Hu,
                    const float* __restrict__ Wsi, const float* __restrict__ bi,
                    float* __restrict__ xwi,
                    const float* __restrict__ Wli, const float* __restrict__ bli,
                    float* __restrict__ Hi,
                    int nu, int ni)
{
    extern __shared__ char smem[];
    const uint32_t sbase = smem_u32(smem);
    float* bs = (float*)(smem + NBS);
    const float4* rawv = (const float4*)(smem + NRAW);

    const int tid  = threadIdx.x;
    const int warp = tid >> 5;
    const int lane = tid & 31;
    const int r0 = (warp >> 1) * 16;
    const int n0 = (warp & 1) * 64;

    const float* Xs_[4] = {Xu, Xu, Xi, Xi};
    const float* Ws_[4] = {Wsu, Wlu, Wsi, Wli};
    const float* bs_[4] = {bu, blu, bi, bli};
    float*       Ys_[4] = {xwu, Hu, xwi, Hi};
    const int    ns_[4] = {nu, nu, ni, ni};

    const int tu = (nu + 127) >> 7;
    const int ti = (ni + 127) >> 7;
    const int cum[5] = {0, tu, 2 * tu, 2 * tu + ti, 2 * tu + 2 * ti};
    const int total = cum[4];
    const int G = gridDim.x;

    const uint32_t a_off = (uint32_t)((r0 + (lane & 15)) * XSTRIDE + (lane >> 4) * 16);
    const int bg = lane >> 3;
    const uint32_t b_off = (uint32_t)(((lane & 7) + (bg & 1) * 8) * XSTRIDE
                                      + (n0 + (bg >> 1) * 8) * 2);

    auto issue_copy = [&](int tt) {
        int seg = (tt >= cum[2]) ? ((tt >= cum[3]) ? 3 : 2)
                                 : ((tt >= cum[1]) ? 1 : 0);
        const float* Xg = Xs_[seg];
        const int n = ns_[seg];
        const int row_base = (tt - cum[seg]) * 128;
        #pragma unroll
        for (int j = 0; j < 8; j++) {
            int idx = tid + j * NT_THREADS;
            int row = idx >> 5, c4 = idx & 31;
            int grow = row_base + row;
            int ok = (grow < n);
            const float* src = Xg + (size_t)(ok ? grow : 0) * 128 + c4 * 4;
            CPA16(sbase + NRAW + idx * 16, src, ok ? 16 : 0);
        }
        CPA_COMMIT();
    };

    int cur_seg = -1;
    int t = blockIdx.x;
    if (t < total) issue_copy(t);

    for (; t < total; t += G) {
        int seg = (t >= cum[2]) ? ((t >= cum[3]) ? 3 : 2)
                                : ((t >= cum[1]) ? 1 : 0);
        const int n = ns_[seg];
        const int row_base = (t - cum[seg]) * 128;
        float* Y = Ys_[seg];

        if (seg != cur_seg) {
            __syncthreads();
            const float4* Wg = (const float4*)Ws_[seg];
            #pragma unroll
            for (int j = 0; j < 8; j++) {
                int idx = tid + j * NT_THREADS;
                int row = idx >> 5, c4 = idx & 31;
                uint2 hi, lo;
                cvt_hi_lo(Wg[row * 32 + c4], hi, lo);
                *(uint2*)(smem + NWHI + row * XSTRIDE + c4 * 8) = hi;
                *(uint2*)(smem + NWLO + row * XSTRIDE + c4 * 8) = lo;
            }
            if (tid < 128) bs[tid] = bs_[seg][tid];
            cur_seg = seg;
        }

        CPA_WAIT0();
        __syncthreads();

        #pragma unroll
        for (int j = 0; j < 8; j++) {
            int idx = tid + j * NT_THREADS;
            int row = idx >> 5, c4 = idx & 31;
            uint2 hi, lo;
            cvt_hi_lo(rawv[idx], hi, lo);
            *(uint2*)(smem + NXHI + row * XSTRIDE + c4 * 8) = hi;
            *(uint2*)(smem + NXLO + row * XSTRIDE + c4 * 8) = lo;
        }
        __syncthreads();

        if (t + G < total) issue_copy(t + G);

        float acc[8][4];
        #pragma unroll
        for (int i = 0; i < 8; i++)
            #pragma unroll
            for (int j = 0; j < 4; j++) acc[i][j] = 0.f;

        #pragma unroll
        for (int k0 = 0; k0 < 128; k0 += 16) {
            uint32_t ah[4], al[4];
            uint32_t aaddr = sbase + NXHI + a_off + k0 * 2;
            LDSM4(ah, aaddr);
            LDSM4(al, aaddr + (NXLO - NXHI));
            #pragma unroll
            for (int c = 0; c < 4; c++) {
                uint32_t bh[4], bl[4];
                uint32_t baddr = sbase + NWHI + b_off + k0 * XSTRIDE + c * 32;
                LDSM4T(bh, baddr);
                LDSM4T(bl, baddr + (NWLO - NWHI));
                MMA16816(acc[2 * c],     ah, bh[0], bh[1]);
                MMA16816(acc[2 * c + 1], ah, bh[2], bh[3]);
                MMA16816(acc[2 * c],     ah, bl[0], bl[1]);
                MMA16816(acc[2 * c + 1], ah, bl[2], bl[3]);
                MMA16816(acc[2 * c],     al, bh[0], bh[1]);
                MMA16816(acc[2 * c + 1], al, bh[2], bh[3]);
            }
        }

        const int ra = row_base + r0 + (lane >> 2);
        const int rb = ra + 8;
        #pragma unroll
        for (int c8 = 0; c8 < 8; c8++) {
            int col = n0 + c8 * 8 + 2 * (lane & 3);
            float b0 = bs[col], b1 = bs[col + 1];
            if (ra < n) {
                float2 v = make_float2(acc[c8][0] + b0, acc[c8][1] + b1);
                *(float2*)(Y + (size_t)ra * 128 + col) = v;
            }
            if (rb < n) {
                float2 v = make_float2(acc[c8][2] + b0, acc[c8][3] + b1);
                *(float2*)(Y + (size_t)rb * 128 + col) = v;
            }
        }
    }
}

// ---------------------------------------------------------------------------
// Relation kernel v9: mma.sync bf16x3 (tensor core), cp.async pipelined.
//   Tile = 64 edges x 128 cols, K=32. 256 threads / 8 warps; warp w:
//   edges (w>>1)*16..+15, cols (w&1)*64..+63 (same fragment map as node_tc).
//   A = Xe hi/lo @ stride 80 (32 bf16 + 16B pad); B = We hi/lo @ stride 272,
//   staged once per block. Epilogue: XW[src] float2 gather + relu + red.v2.
//   blockIdx.y picks the relation.
// ---------------------------------------------------------------------------
#define RT_THREADS 256
#define RT_TILE 64
#define ASTR 80
#define RB_HI 0
#define RB_LO 8704
#define RA_HI 17408
#define RA_LO 27648
#define RRAW  37888
#define RS_   46080
#define RD_   46336
#define RT_SMEM_BYTES 46592

__global__ __launch_bounds__(RT_THREADS, 2)
void rel_tc_kernel(const float* __restrict__ XW0, const float* __restrict__ Xe0,
                   const int* __restrict__ src0, const int* __restrict__ dst0,
                   const float* __restrict__ We0, float* __restrict__ out0,
                   const float* __restrict__ XW1, const float* __restrict__ Xe1,
                   const int* __restrict__ src1, const int* __restrict__ dst1,
                   const float* __restrict__ We1, float* __restrict__ out1,
                   int E)
{
    const float* XW = blockIdx.y ? XW1 : XW0;
    const float* Xe = blockIdx.y ? Xe1 : Xe0;
    const int*  src = blockIdx.y ? src1 : src0;
    const int*  dst = blockIdx.y ? dst1 : dst0;
    const float* We = blockIdx.y ? We1 : We0;
    float*      out = blockIdx.y ? out1 : out0;

    __shared__ __align__(16) char smem[RT_SMEM_BYTES];
    const uint32_t sbase = smem_u32(smem);
    const float4* rawv = (const float4*)(smem + RRAW);
    int* Ss = (int*)(smem + RS_);
    int* Ds = (int*)(smem + RD_);

    const int tid  = threadIdx.x;
    const int warp = tid >> 5;
    const int lane = tid & 31;
    const int r0 = (warp >> 1) * 16;        // edge-row base (4 groups of 16)
    const int n0 = (warp & 1) * 64;         // col half

    // Stage B = We (32 x 128) as bf16 hi/lo once per block.
    #pragma unroll
    for (int j = 0; j < 4; j++) {
        int idx = tid + j * RT_THREADS;     // 1024 float4 chunks
        int row = idx >> 5, c4 = idx & 31;
        uint2 hi, lo;
        cvt_hi_lo(((const float4*)We)[row * 32 + c4], hi, lo);
        *(uint2*)(smem + RB_HI + row * XSTRIDE + c4 * 8) = hi;
        *(uint2*)(smem + RB_LO + row * XSTRIDE + c4 * 8) = lo;
    }

    // ldmatrix lane addresses.
    const uint32_t a_off = (uint32_t)((r0 + (lane & 15)) * ASTR + (lane >> 4) * 16);
    const int bg = lane >> 3;
    const uint32_t b_off = (uint32_t)(((lane & 7) + (bg & 1) * 8) * XSTRIDE
                                      + (n0 + (bg >> 1) * 8) * 2);

    const int ntiles = (E + RT_TILE - 1) / RT_TILE;
    const int G = gridDim.x;

    auto issue_raw = [&](int tt) {
        int e0 = tt * RT_TILE;
        #pragma unroll
        for (int j = 0; j < 2; j++) {
            int idx = tid + j * RT_THREADS;     // 512 chunks: edge=idx>>3
            int e = e0 + (idx >> 3);
            int ok = (e < E);
            const float* g = Xe + (size_t)(ok ? e : 0) * 32 + (idx & 7) * 4;
            CPA16(sbase + RRAW + idx * 16, g, ok ? 16 : 0);
        }
        CPA_COMMIT();
    };
    auto load_idx = [&](int tt) -> int {
        if (tt < ntiles) {
            if (tid < RT_TILE) {
                int e = tt * RT_TILE + tid;
                return (e < E) ? __ldg(src + e) : 0;
            } else if (tid < 2 * RT_TILE) {
                int e = tt * RT_TILE + tid - RT_TILE;
                return (e < E) ? __ldg(dst + e) : 0;
            }
        }
        return 0;
    };

    int t = blockIdx.x;
    if (t < ntiles) issue_raw(t);
    int pidx = load_idx(t);
    __syncthreads();            // B staged

    for (; t < ntiles; t += G) {
        const int e0 = t * RT_TILE;

        CPA_WAIT0();            // raw Xe[t] landed
        __syncthreads();        // prev tile's A readers + epilogue idx readers done

        // Convert raw Xe -> A hi/lo; store indices.
        #pragma unroll
        for (int j = 0; j < 2; j++) {
            int idx = tid + j * RT_THREADS;
            int row = idx >> 3, c4 = idx & 7;
            uint2 hi, lo;
            cvt_hi_lo(rawv[idx], hi, lo);
            *(uint2*)(smem + RA_HI + row * ASTR + c4 * 8) = hi;
            *(uint2*)(smem + RA_LO + row * ASTR + c4 * 8) = lo;
        }
        if (tid < RT_TILE) Ss[tid] = pidx;
        else if (tid < 2 * RT_TILE) Ds[tid - RT_TILE] = pidx;
        __syncthreads();

        // Grab this thread's edge indices before the next async copy cycle.
        const int er = r0 + (lane >> 2);
        int s_a = Ss[er],     d_a = Ds[er];
        int s_b = Ss[er + 8], d_b = Ds[er + 8];

        // Kick next tile's raw copy + index loads (stream under MMA).
        if (t + G < ntiles) issue_raw(t + G);
        pidx = load_idx(t + G);

        float acc[8][4];
        #pragma unroll
        for (int i = 0; i < 8; i++)
            #pragma unroll
            for (int j = 0; j < 4; j++) acc[i][j] = 0.f;

        #pragma unroll
        for (int k0 = 0; k0 < 32; k0 += 16) {
            uint32_t ah[4], al[4];
            uint32_t aaddr = sbase + RA_HI + a_off + k0 * 2;
            LDSM4(ah, aaddr);
            LDSM4(al, aaddr + (RA_LO - RA_HI));
            #pragma unroll
            for (int c = 0; c < 4; c++) {
                uint32_t bh[4], bl[4];
                uint32_t baddr = sbase + RB_HI + b_off + k0 * XSTRIDE + c * 32;
                LDSM4T(bh, baddr);
                LDSM4T(bl, baddr + (RB_LO - RB_HI));
                MMA16816(acc[2 * c],     ah, bh[0], bh[1]);
                MMA16816(acc[2 * c + 1], ah, bh[2], bh[3]);
                MMA16816(acc[2 * c],     ah, bl[0], bl[1]);
                MMA16816(acc[2 * c + 1], ah, bl[2], bl[3]);
                MMA16816(acc[2 * c],     al, bh[0], bh[1]);
                MMA16816(acc[2 * c + 1], al, bh[2], bh[3]);
            }
        }

        // Epilogue: + XW[src] (bias folded), relu, scatter-add.
        const int ea = e0 + er;
        const int eb = ea + 8;
        const float* ga = XW + (size_t)s_a * 128;
        const float* gb = XW + (size_t)s_b * 128;
        float* oa = out + (size_t)d_a * 128;
        float* ob = out + (size_t)d_b * 128;
        #pragma unroll
        for (int c8 = 0; c8 < 8; c8++) {
            int col = n0 + c8 * 8 + 2 * (lane & 3);
            if (ea < E) {
                float2 g = *(const float2*)(ga + col);
                float v0 = fmaxf(acc[c8][0] + g.x, 0.f);
                float v1 = fmaxf(acc[c8][1] + g.y, 0.f);
                RED_V2(oa + col, v0, v1);
            }
            if (eb < E) {
                float2 g = *(const float2*)(gb + col);
                float v0 = fmaxf(acc[c8][2] + g.x, 0.f);
                float v1 = fmaxf(acc[c8][3] + g.y, 0.f);
                RED_V2(ob + col, v0, v1);
            }
        }
    }
}

// ---------------------------------------------------------------------------
// kernel_launch (metadata order unchanged)
// ---------------------------------------------------------------------------
extern "C" void kernel_launch(void* const* d_in, const int* in_sizes, int n_in,
                              void* d_out, int out_size)
{
    const float* X_user   = (const float*)d_in[0];
    const float* X_item   = (const float*)d_in[1];
    const float* Xe_ui    = (const float*)d_in[2];
    const float* Xe_iu    = (const float*)d_in[3];
    const float* W_src_ui = (const float*)d_in[4];
    const float* W_edge_ui= (const float*)d_in[5];
    const float* b_ui     = (const float*)d_in[6];
    const float* W_src_iu = (const float*)d_in[7];
    const float* W_edge_iu= (const float*)d_in[8];
    const float* b_iu     = (const float*)d_in[9];
    const float* Wl_user  = (const float*)d_in[10];
    const float* bl_user  = (const float*)d_in[11];
    const float* Wl_item  = (const float*)d_in[12];
    const float* bl_item  = (const float*)d_in[13];
    const int*   src_ui   = (const int*)d_in[14];
    const int*   dst_ui   = (const int*)d_in[15];
    const int*   src_iu   = (const int*)d_in[16];
    const int*   dst_iu   = (const int*)d_in[17];

    const int n_user = in_sizes[0] / D_IN;
    const int n_item = in_sizes[1] / D_IN;
    const int E      = in_sizes[14];

    float* H_user = (float*)d_out;
    float* H_item = (float*)d_out + (size_t)n_user * D_OUT;

    void* p_xwu = nullptr; void* p_xwi = nullptr;
    cudaGetSymbolAddress(&p_xwu, g_xwu);
    cudaGetSymbolAddress(&p_xwi, g_xwi);
    float* xwu = (float*)p_xwu;
    float* xwi = (float*)p_xwi;

    cudaFuncSetAttribute(node_tc_kernel,
                         cudaFuncAttributeMaxDynamicSharedMemorySize,
                         NT_SMEM);

    node_tc_kernel<<<148, NT_THREADS, NT_SMEM>>>(
        X_user, X_item,
        W_src_ui, b_ui, xwu,
        Wl_user, bl_user, H_user,
        W_src_iu, b_iu, xwi,
        Wl_item, bl_item, H_item,
        n_user, n_item);

    dim3 grel(148, 2);   // 2 blocks/SM (one per relation stream)
    rel_tc_kernel<<<grel, RT_THREADS>>>(
        xwu, Xe_ui, src_ui, dst_ui, W_edge_ui, H_item,
        xwi, Xe_iu, src_iu, dst_iu, W_edge_iu, H_user,
        E);
}

// round 12
// speedup vs baseline: 1.1779x; 1.1779x over previous
#include <cuda_runtime.h>
#include <cuda_bf16.h>
#include <cstdint>
#include <cstddef>

#define D_IN   128
#define D_OUT  128
#define D_EDGE 32
#define MAX_NODES 100000

__device__ float g_xwu[(size_t)MAX_NODES * D_OUT];
__device__ float g_xwi[(size_t)MAX_NODES * D_OUT];

// ============================= common helpers ==============================
__device__ __forceinline__ uint32_t smem_u32(const void* p) {
    uint32_t a;
    asm("{ .reg .u64 t; cvta.to.shared.u64 t, %1; cvt.u32.u64 %0, t; }"
        : "=r"(a) : "l"(p));
    return a;
}
__device__ __forceinline__ uint32_t bf2bits(__nv_bfloat162 h) {
    return *reinterpret_cast<uint32_t*>(&h);
}
__device__ __forceinline__ void cvt_hi_lo(float4 x, uint2& hi, uint2& lo) {
    __nv_bfloat162 h01 = __floats2bfloat162_rn(x.x, x.y);
    __nv_bfloat162 h23 = __floats2bfloat162_rn(x.z, x.w);
    float2 f01 = __bfloat1622float2(h01);
    float2 f23 = __bfloat1622float2(h23);
    __nv_bfloat162 l01 = __floats2bfloat162_rn(x.x - f01.x, x.y - f01.y);
    __nv_bfloat162 l23 = __floats2bfloat162_rn(x.z - f23.x, x.w - f23.y);
    hi = make_uint2(bf2bits(h01), bf2bits(h23));
    lo = make_uint2(bf2bits(l01), bf2bits(l23));
}

#define LDSM4(r, addr) \
    asm volatile("ldmatrix.sync.aligned.m8n8.x4.shared.b16 {%0,%1,%2,%3}, [%4];" \
        : "=r"((r)[0]), "=r"((r)[1]), "=r"((r)[2]), "=r"((r)[3]) : "r"(addr))
#define LDSM4T(r, addr) \
    asm volatile("ldmatrix.sync.aligned.m8n8.x4.trans.shared.b16 {%0,%1,%2,%3}, [%4];" \
        : "=r"((r)[0]), "=r"((r)[1]), "=r"((r)[2]), "=r"((r)[3]) : "r"(addr))
#define MMA16816(c, a, b0_, b1_) \
    asm volatile("mma.sync.aligned.m16n8k16.row.col.f32.bf16.bf16.f32 " \
        "{%0,%1,%2,%3}, {%4,%5,%6,%7}, {%8,%9}, {%0,%1,%2,%3};" \
        : "+f"((c)[0]), "+f"((c)[1]), "+f"((c)[2]), "+f"((c)[3]) \
        : "r"((a)[0]), "r"((a)[1]), "r"((a)[2]), "r"((a)[3]), "r"(b0_), "r"(b1_))

#define CPA16(s, g, sz) \
    asm volatile("cp.async.cg.shared.global [%0], [%1], 16, %2;" \
                 :: "r"(s), "l"(g), "r"(sz) : "memory")
#define CPA_COMMIT() asm volatile("cp.async.commit_group;" ::: "memory")
#define CPA_WAIT0()  asm volatile("cp.async.wait_group 0;" ::: "memory")

__device__ __forceinline__ void red_add_v4(float* p, float4 v) {
    asm volatile("red.global.add.v4.f32 [%0], {%1,%2,%3,%4};"
                 :: "l"(p), "f"(v.x), "f"(v.y), "f"(v.z), "f"(v.w)
                 : "memory");
}

// ---------------------------------------------------------------------------
// Node stage (R10, unchanged): tensor-core + cp.async pipelined, 4 fused GEMMs.
// ---------------------------------------------------------------------------
#define NT_THREADS 512
#define XSTRIDE    272
#define NXHI 0
#define NXLO 34816
#define NWHI 69632
#define NWLO 104448
#define NRAW 139264
#define NBS  204800
#define NT_SMEM (NBS + 512)

__global__ __launch_bounds__(NT_THREADS, 1)
void node_tc_kernel(const float* __restrict__ Xu, const float* __restrict__ Xi,
                    const float* __restrict__ Wsu, const float* __restrict__ bu,
                    float* __restrict__ xwu,
                    const float* __restrict__ Wlu, const float* __restrict__ blu,
                    float* __restrict__ Hu,
                    const float* __restrict__ Wsi, const float* __restrict__ bi,
                    float* __restrict__ xwi,
                    const float* __restrict__ Wli, const float* __restrict__ bli,
                    float* __restrict__ Hi,
                    int nu, int ni)
{
    extern __shared__ char smem[];
    const uint32_t sbase = smem_u32(smem);
    float* bs = (float*)(smem + NBS);
    const float4* rawv = (const float4*)(smem + NRAW);

    const int tid  = threadIdx.x;
    const int warp = tid >> 5;
    const int lane = tid & 31;
    const int r0 = (warp >> 1) * 16;
    const int n0 = (warp & 1) * 64;

    const float* Xs_[4] = {Xu, Xu, Xi, Xi};
    const float* Ws_[4] = {Wsu, Wlu, Wsi, Wli};
    const float* bs_[4] = {bu, blu, bi, bli};
    float*       Ys_[4] = {xwu, Hu, xwi, Hi};
    const int    ns_[4] = {nu, nu, ni, ni};

    const int tu = (nu + 127) >> 7;
    const int ti = (ni + 127) >> 7;
    const int cum[5] = {0, tu, 2 * tu, 2 * tu + ti, 2 * tu + 2 * ti};
    const int total = cum[4];
    const int G = gridDim.x;

    const uint32_t a_off = (uint32_t)((r0 + (lane & 15)) * XSTRIDE + (lane >> 4) * 16);
    const int bg = lane >> 3;
    const uint32_t b_off = (uint32_t)(((lane & 7) + (bg & 1) * 8) * XSTRIDE
                                      + (n0 + (bg >> 1) * 8) * 2);

    auto issue_copy = [&](int tt) {
        int seg = (tt >= cum[2]) ? ((tt >= cum[3]) ? 3 : 2)
                                 : ((tt >= cum[1]) ? 1 : 0);
        const float* Xg = Xs_[seg];
        const int n = ns_[seg];
        const int row_base = (tt - cum[seg]) * 128;
        #pragma unroll
        for (int j = 0; j < 8; j++) {
            int idx = tid + j * NT_THREADS;
            int row = idx >> 5, c4 = idx & 31;
            int grow = row_base + row;
            int ok = (grow < n);
            const float* src = Xg + (size_t)(ok ? grow : 0) * 128 + c4 * 4;
            CPA16(sbase + NRAW + idx * 16, src, ok ? 16 : 0);
        }
        CPA_COMMIT();
    };

    int cur_seg = -1;
    int t = blockIdx.x;
    if (t < total) issue_copy(t);

    for (; t < total; t += G) {
        int seg = (t >= cum[2]) ? ((t >= cum[3]) ? 3 : 2)
                                : ((t >= cum[1]) ? 1 : 0);
        const int n = ns_[seg];
        const int row_base = (t - cum[seg]) * 128;
        float* Y = Ys_[seg];

        if (seg != cur_seg) {
            __syncthreads();
            const float4* Wg = (const float4*)Ws_[seg];
            #pragma unroll
            for (int j = 0; j < 8; j++) {
                int idx = tid + j * NT_THREADS;
                int row = idx >> 5, c4 = idx & 31;
                uint2 hi, lo;
                cvt_hi_lo(Wg[row * 32 + c4], hi, lo);
                *(uint2*)(smem + NWHI + row * XSTRIDE + c4 * 8) = hi;
                *(uint2*)(smem + NWLO + row * XSTRIDE + c4 * 8) = lo;
            }
            if (tid < 128) bs[tid] = bs_[seg][tid];
            cur_seg = seg;
        }

        CPA_WAIT0();
        __syncthreads();

        #pragma unroll
        for (int j = 0; j < 8; j++) {
            int idx = tid + j * NT_THREADS;
            int row = idx >> 5, c4 = idx & 31;
            uint2 hi, lo;
            cvt_hi_lo(rawv[idx], hi, lo);
            *(uint2*)(smem + NXHI + row * XSTRIDE + c4 * 8) = hi;
            *(uint2*)(smem + NXLO + row * XSTRIDE + c4 * 8) = lo;
        }
        __syncthreads();

        if (t + G < total) issue_copy(t + G);

        float acc[8][4];
        #pragma unroll
        for (int i = 0; i < 8; i++)
            #pragma unroll
            for (int j = 0; j < 4; j++) acc[i][j] = 0.f;

        #pragma unroll
        for (int k0 = 0; k0 < 128; k0 += 16) {
            uint32_t ah[4], al[4];
            uint32_t aaddr = sbase + NXHI + a_off + k0 * 2;
            LDSM4(ah, aaddr);
            LDSM4(al, aaddr + (NXLO - NXHI));
            #pragma unroll
            for (int c = 0; c < 4; c++) {
                uint32_t bh[4], bl[4];
                uint32_t baddr = sbase + NWHI + b_off + k0 * XSTRIDE + c * 32;
                LDSM4T(bh, baddr);
                LDSM4T(bl, baddr + (NWLO - NWHI));
                MMA16816(acc[2 * c],     ah, bh[0], bh[1]);
                MMA16816(acc[2 * c + 1], ah, bh[2], bh[3]);
                MMA16816(acc[2 * c],     ah, bl[0], bl[1]);
                MMA16816(acc[2 * c + 1], ah, bl[2], bl[3]);
                MMA16816(acc[2 * c],     al, bh[0], bh[1]);
                MMA16816(acc[2 * c + 1], al, bh[2], bh[3]);
            }
        }

        const int ra = row_base + r0 + (lane >> 2);
        const int rb = ra + 8;
        #pragma unroll
        for (int c8 = 0; c8 < 8; c8++) {
            int col = n0 + c8 * 8 + 2 * (lane & 3);
            float b0 = bs[col], b1 = bs[col + 1];
            if (ra < n) {
                float2 v = make_float2(acc[c8][0] + b0, acc[c8][1] + b1);
                *(float2*)(Y + (size_t)ra * 128 + col) = v;
            }
            if (rb < n) {
                float2 v = make_float2(acc[c8][2] + b0, acc[c8][3] + b1);
                *(float2*)(Y + (size_t)rb * 128 + col) = v;
            }
        }
    }
}

// ---------------------------------------------------------------------------
// Relation kernel v10: mma.sync bf16x3 + smem-transposed COALESCED epilogue.
//   Tile = 64 edges x 128 cols, K=32. 256 threads / 8 warps.
//   MMA fragments -> Tacc[64][136] fp32 in smem -> sync -> each warp owns
//   8 whole edges: LDS.128 row + LDG.128 XW[src] (512B coalesced) + relu +
//   red.v4 (512B segments). cp.async double-buffers raw Xe.
// ---------------------------------------------------------------------------
#define RT_THREADS 256
#define RT_TILE 64
#define ASTR 80
#define TSTR 136
#define RB_HI 0
#define RB_LO 8704
#define RA_HI 17408
#define RA_LO 22528
#define RRAW  27648
#define RTACC 35840
#define RS_   (RTACC + RT_TILE * TSTR * 4)   // 35840 + 34816 = 70656
#define RD_   (RS_ + 256)
#define RT_SMEM (RD_ + 256)                  // 71168

__global__ __launch_bounds__(RT_THREADS, 2)
void rel_tc_kernel(const float* __restrict__ XW0, const float* __restrict__ Xe0,
                   const int* __restrict__ src0, const int* __restrict__ dst0,
                   const float* __restrict__ We0, float* __restrict__ out0,
                   const float* __restrict__ XW1, const float* __restrict__ Xe1,
                   const int* __restrict__ src1, const int* __restrict__ dst1,
                   const float* __restrict__ We1, float* __restrict__ out1,
                   int E)
{
    const float* XW = blockIdx.y ? XW1 : XW0;
    const float* Xe = blockIdx.y ? Xe1 : Xe0;
    const int*  src = blockIdx.y ? src1 : src0;
    const int*  dst = blockIdx.y ? dst1 : dst0;
    const float* We = blockIdx.y ? We1 : We0;
    float*      out = blockIdx.y ? out1 : out0;

    extern __shared__ char smem[];
    const uint32_t sbase = smem_u32(smem);
    const float4* rawv = (const float4*)(smem + RRAW);
    float* Tacc = (float*)(smem + RTACC);
    int* Ss = (int*)(smem + RS_);
    int* Ds = (int*)(smem + RD_);

    const int tid  = threadIdx.x;
    const int warp = tid >> 5;
    const int lane = tid & 31;
    const int r0 = (warp >> 1) * 16;
    const int n0 = (warp & 1) * 64;

    // Stage B = We (32 x 128) as bf16 hi/lo once per block.
    #pragma unroll
    for (int j = 0; j < 4; j++) {
        int idx = tid + j * RT_THREADS;
        int row = idx >> 5, c4 = idx & 31;
        uint2 hi, lo;
        cvt_hi_lo(((const float4*)We)[row * 32 + c4], hi, lo);
        *(uint2*)(smem + RB_HI + row * XSTRIDE + c4 * 8) = hi;
        *(uint2*)(smem + RB_LO + row * XSTRIDE + c4 * 8) = lo;
    }

    const uint32_t a_off = (uint32_t)((r0 + (lane & 15)) * ASTR + (lane >> 4) * 16);
    const int bg = lane >> 3;
    const uint32_t b_off = (uint32_t)(((lane & 7) + (bg & 1) * 8) * XSTRIDE
                                      + (n0 + (bg >> 1) * 8) * 2);

    const int ntiles = (E + RT_TILE - 1) / RT_TILE;
    const int G = gridDim.x;

    auto issue_raw = [&](int tt) {
        int e0 = tt * RT_TILE;
        #pragma unroll
        for (int j = 0; j < 2; j++) {
            int idx = tid + j * RT_THREADS;
            int e = e0 + (idx >> 3);
            int ok = (e < E);
            const float* g = Xe + (size_t)(ok ? e : 0) * 32 + (idx & 7) * 4;
            CPA16(sbase + RRAW + idx * 16, g, ok ? 16 : 0);
        }
        CPA_COMMIT();
    };
    auto load_idx = [&](int tt) -> int {
        if (tt < ntiles) {
            if (tid < RT_TILE) {
                int e = tt * RT_TILE + tid;
                return (e < E) ? __ldg(src + e) : 0;
            } else if (tid < 2 * RT_TILE) {
                int e = tt * RT_TILE + tid - RT_TILE;
                return (e < E) ? __ldg(dst + e) : 0;
            }
        }
        return 0;
    };

    int t = blockIdx.x;
    if (t < ntiles) issue_raw(t);
    int pidx = load_idx(t);
    __syncthreads();            // B staged

    for (; t < ntiles; t += G) {
        const int e0 = t * RT_TILE;

        CPA_WAIT0();            // raw Xe[t] landed
        __syncthreads();        // prev tile's Tacc/Ss readers done

        // Convert raw Xe -> A hi/lo; publish indices.
        #pragma unroll
        for (int j = 0; j < 2; j++) {
            int idx = tid + j * RT_THREADS;
            int row = idx >> 3, c4 = idx & 7;
            uint2 hi, lo;
            cvt_hi_lo(rawv[idx], hi, lo);
            *(uint2*)(smem + RA_HI + row * ASTR + c4 * 8) = hi;
            *(uint2*)(smem + RA_LO + row * ASTR + c4 * 8) = lo;
        }
        if (tid < RT_TILE) Ss[tid] = pidx;
        else if (tid < 2 * RT_TILE) Ds[tid - RT_TILE] = pidx;
        __syncthreads();

        // Kick next tile's raw copy + index loads (stream under MMA).
        if (t + G < ntiles) issue_raw(t + G);
        pidx = load_idx(t + G);

        float acc[8][4];
        #pragma unroll
        for (int i = 0; i < 8; i++)
            #pragma unroll
            for (int j = 0; j < 4; j++) acc[i][j] = 0.f;

        #pragma unroll
        for (int k0 = 0; k0 < 32; k0 += 16) {
            uint32_t ah[4], al[4];
            uint32_t aaddr = sbase + RA_HI + a_off + k0 * 2;
            LDSM4(ah, aaddr);
            LDSM4(al, aaddr + (RA_LO - RA_HI));
            #pragma unroll
            for (int c = 0; c < 4; c++) {
                uint32_t bh[4], bl[4];
                uint32_t baddr = sbase + RB_HI + b_off + k0 * XSTRIDE + c * 32;
                LDSM4T(bh, baddr);
                LDSM4T(bl, baddr + (RB_LO - RB_HI));
                MMA16816(acc[2 * c],     ah, bh[0], bh[1]);
                MMA16816(acc[2 * c + 1], ah, bh[2], bh[3]);
                MMA16816(acc[2 * c],     ah, bl[0], bl[1]);
                MMA16816(acc[2 * c + 1], ah, bl[2], bl[3]);
                MMA16816(acc[2 * c],     al, bh[0], bh[1]);
                MMA16816(acc[2 * c + 1], al, bh[2], bh[3]);
            }
        }

        // Transpose fragments into Tacc (row = edge-in-tile, 136f stride).
        {
            const int era = r0 + (lane >> 2);
            #pragma unroll
            for (int c8 = 0; c8 < 8; c8++) {
                int col = n0 + c8 * 8 + 2 * (lane & 3);
                *(float2*)(Tacc + era * TSTR + col) =
                    make_float2(acc[c8][0], acc[c8][1]);
                *(float2*)(Tacc + (era + 8) * TSTR + col) =
                    make_float2(acc[c8][2], acc[c8][3]);
            }
        }
        __syncthreads();

        // Coalesced epilogue: warp owns edges warp*8 .. +7.
        #pragma unroll
        for (int i = 0; i < 8; i++) {
            int el = warp * 8 + i;
            int e = e0 + el;
            if (e < E) {
                int s = Ss[el];
                int d = Ds[el];
                float4 v = *(float4*)(Tacc + el * TSTR + 4 * lane);
                float4 g = __ldg((const float4*)(XW + (size_t)s * 128) + lane);
                v.x = fmaxf(v.x + g.x, 0.f);
                v.y = fmaxf(v.y + g.y, 0.f);
                v.z = fmaxf(v.z + g.z, 0.f);
                v.w = fmaxf(v.w + g.w, 0.f);
                red_add_v4(out + (size_t)d * 128 + 4 * lane, v);
            }
        }
    }
}

// ---------------------------------------------------------------------------
// kernel_launch (metadata order unchanged)
// ---------------------------------------------------------------------------
extern "C" void kernel_launch(void* const* d_in, const int* in_sizes, int n_in,
                              void* d_out, int out_size)
{
    const float* X_user   = (const float*)d_in[0];
    const float* X_item   = (const float*)d_in[1];
    const float* Xe_ui    = (const float*)d_in[2];
    const float* Xe_iu    = (const float*)d_in[3];
    const float* W_src_ui = (const float*)d_in[4];
    const float* W_edge_ui= (const float*)d_in[5];
    const float* b_ui     = (const float*)d_in[6];
    const float* W_src_iu = (const float*)d_in[7];
    const float* W_edge_iu= (const float*)d_in[8];
    const float* b_iu     = (const float*)d_in[9];
    const float* Wl_user  = (const float*)d_in[10];
    const float* bl_user  = (const float*)d_in[11];
    const float* Wl_item  = (const float*)d_in[12];
    const float* bl_item  = (const float*)d_in[13];
    const int*   src_ui   = (const int*)d_in[14];
    const int*   dst_ui   = (const int*)d_in[15];
    const int*   src_iu   = (const int*)d_in[16];
    const int*   dst_iu   = (const int*)d_in[17];

    const int n_user = in_sizes[0] / D_IN;
    const int n_item = in_sizes[1] / D_IN;
    const int E      = in_sizes[14];

    float* H_user = (float*)d_out;
    float* H_item = (float*)d_out + (size_t)n_user * D_OUT;

    void* p_xwu = nullptr; void* p_xwi = nullptr;
    cudaGetSymbolAddress(&p_xwu, g_xwu);
    cudaGetSymbolAddress(&p_xwi, g_xwi);
    float* xwu = (float*)p_xwu;
    float* xwi = (float*)p_xwi;

    cudaFuncSetAttribute(node_tc_kernel,
                         cudaFuncAttributeMaxDynamicSharedMemorySize,
                         NT_SMEM);
    cudaFuncSetAttribute(rel_tc_kernel,
                         cudaFuncAttributeMaxDynamicSharedMemorySize,
                         RT_SMEM);

    node_tc_kernel<<<148, NT_THREADS, NT_SMEM>>>(
        X_user, X_item,
        W_src_ui, b_ui, xwu,
        Wl_user, bl_user, H_user,
        W_src_iu, b_iu, xwi,
        Wl_item, bl_item, H_item,
        n_user, n_item);

    dim3 grel(148, 2);   // 2 blocks/SM
    rel_tc_kernel<<<grel, RT_THREADS, RT_SMEM>>>(
        xwu, Xe_ui, src_ui, dst_ui, W_edge_ui, H_item,
        xwi, Xe_iu, src_iu, dst_iu, W_edge_iu, H_user,
        E);
}

// round 13
// speedup vs baseline: 1.7229x; 1.4626x over previous
#include <cuda_runtime.h>
#include <cuda_bf16.h>
#include <cstdint>
#include <cstddef>

#define D_IN   128
#define D_OUT  128
#define D_EDGE 32
#define MAX_NODES 100000

__device__ float g_xwu[(size_t)MAX_NODES * D_OUT];
__device__ float g_xwi[(size_t)MAX_NODES * D_OUT];

// ============================= common helpers ==============================
__device__ __forceinline__ uint32_t smem_u32(const void* p) {
    uint32_t a;
    asm("{ .reg .u64 t; cvta.to.shared.u64 t, %1; cvt.u32.u64 %0, t; }"
        : "=r"(a) : "l"(p));
    return a;
}
__device__ __forceinline__ uint32_t bf2bits(__nv_bfloat162 h) {
    return *reinterpret_cast<uint32_t*>(&h);
}
__device__ __forceinline__ void cvt_hi_lo(float4 x, uint2& hi, uint2& lo) {
    __nv_bfloat162 h01 = __floats2bfloat162_rn(x.x, x.y);
    __nv_bfloat162 h23 = __floats2bfloat162_rn(x.z, x.w);
    float2 f01 = __bfloat1622float2(h01);
    float2 f23 = __bfloat1622float2(h23);
    __nv_bfloat162 l01 = __floats2bfloat162_rn(x.x - f01.x, x.y - f01.y);
    __nv_bfloat162 l23 = __floats2bfloat162_rn(x.z - f23.x, x.w - f23.y);
    hi = make_uint2(bf2bits(h01), bf2bits(h23));
    lo = make_uint2(bf2bits(l01), bf2bits(l23));
}

#define LDSM4(r, addr) \
    asm volatile("ldmatrix.sync.aligned.m8n8.x4.shared.b16 {%0,%1,%2,%3}, [%4];" \
        : "=r"((r)[0]), "=r"((r)[1]), "=r"((r)[2]), "=r"((r)[3]) : "r"(addr))
#define LDSM4T(r, addr) \
    asm volatile("ldmatrix.sync.aligned.m8n8.x4.trans.shared.b16 {%0,%1,%2,%3}, [%4];" \
        : "=r"((r)[0]), "=r"((r)[1]), "=r"((r)[2]), "=r"((r)[3]) : "r"(addr))
#define MMA16816(c, a, b0_, b1_) \
    asm volatile("mma.sync.aligned.m16n8k16.row.col.f32.bf16.bf16.f32 " \
        "{%0,%1,%2,%3}, {%4,%5,%6,%7}, {%8,%9}, {%0,%1,%2,%3};" \
        : "+f"((c)[0]), "+f"((c)[1]), "+f"((c)[2]), "+f"((c)[3]) \
        : "r"((a)[0]), "r"((a)[1]), "r"((a)[2]), "r"((a)[3]), "r"(b0_), "r"(b1_))

#define CPA16(s, g, sz) \
    asm volatile("cp.async.cg.shared.global [%0], [%1], 16, %2;" \
                 :: "r"(s), "l"(g), "r"(sz) : "memory")
#define CPA4(s, g, sz) \
    asm volatile("cp.async.ca.shared.global [%0], [%1], 4, %2;" \
                 :: "r"(s), "l"(g), "r"(sz) : "memory")
#define CPA_COMMIT() asm volatile("cp.async.commit_group;" ::: "memory")
#define CPA_WAIT0()  asm volatile("cp.async.wait_group 0;" ::: "memory")
#define CPA_WAIT1()  asm volatile("cp.async.wait_group 1;" ::: "memory")

__device__ __forceinline__ void red_add_v4(float* p, float4 v) {
    asm volatile("red.global.add.v4.f32 [%0], {%1,%2,%3,%4};"
                 :: "l"(p), "f"(v.x), "f"(v.y), "f"(v.z), "f"(v.w)
                 : "memory");
}

// ---------------------------------------------------------------------------
// Node stage (R10, unchanged): tensor-core + cp.async pipelined, 4 fused GEMMs.
// ---------------------------------------------------------------------------
#define NT_THREADS 512
#define XSTRIDE    272
#define NXHI 0
#define NXLO 34816
#define NWHI 69632
#define NWLO 104448
#define NRAW 139264
#define NBS  204800
#define NT_SMEM (NBS + 512)

__global__ __launch_bounds__(NT_THREADS, 1)
void node_tc_kernel(const float* __restrict__ Xu, const float* __restrict__ Xi,
                    const float* __restrict__ Wsu, const float* __restrict__ bu,
                    float* __restrict__ xwu,
                    const float* __restrict__ Wlu, const float* __restrict__ blu,
                    float* __restrict__ Hu,
                    const float* __restrict__ Wsi, const float* __restrict__ bi,
                    float* __restrict__ xwi,
                    const float* __restrict__ Wli, const float* __restrict__ bli,
                    float* __restrict__ Hi,
                    int nu, int ni)
{
    extern __shared__ char smem[];
    const uint32_t sbase = smem_u32(smem);
    float* bs = (float*)(smem + NBS);
    const float4* rawv = (const float4*)(smem + NRAW);

    const int tid  = threadIdx.x;
    const int warp = tid >> 5;
    const int lane = tid & 31;
    const int r0 = (warp >> 1) * 16;
    const int n0 = (warp & 1) * 64;

    const float* Xs_[4] = {Xu, Xu, Xi, Xi};
    const float* Ws_[4] = {Wsu, Wlu, Wsi, Wli};
    const float* bs_[4] = {bu, blu, bi, bli};
    float*       Ys_[4] = {xwu, Hu, xwi, Hi};
    const int    ns_[4] = {nu, nu, ni, ni};

    const int tu = (nu + 127) >> 7;
    const int ti = (ni + 127) >> 7;
    const int cum[5] = {0, tu, 2 * tu, 2 * tu + ti, 2 * tu + 2 * ti};
    const int total = cum[4];
    const int G = gridDim.x;

    const uint32_t a_off = (uint32_t)((r0 + (lane & 15)) * XSTRIDE + (lane >> 4) * 16);
    const int bg = lane >> 3;
    const uint32_t b_off = (uint32_t)(((lane & 7) + (bg & 1) * 8) * XSTRIDE
                                      + (n0 + (bg >> 1) * 8) * 2);

    auto issue_copy = [&](int tt) {
        int seg = (tt >= cum[2]) ? ((tt >= cum[3]) ? 3 : 2)
                                 : ((tt >= cum[1]) ? 1 : 0);
        const float* Xg = Xs_[seg];
        const int n = ns_[seg];
        const int row_base = (tt - cum[seg]) * 128;
        #pragma unroll
        for (int j = 0; j < 8; j++) {
            int idx = tid + j * NT_THREADS;
            int row = idx >> 5, c4 = idx & 31;
            int grow = row_base + row;
            int ok = (grow < n);
            const float* src = Xg + (size_t)(ok ? grow : 0) * 128 + c4 * 4;
            CPA16(sbase + NRAW + idx * 16, src, ok ? 16 : 0);
        }
        CPA_COMMIT();
    };

    int cur_seg = -1;
    int t = blockIdx.x;
    if (t < total) issue_copy(t);

    for (; t < total; t += G) {
        int seg = (t >= cum[2]) ? ((t >= cum[3]) ? 3 : 2)
                                : ((t >= cum[1]) ? 1 : 0);
        const int n = ns_[seg];
        const int row_base = (t - cum[seg]) * 128;
        float* Y = Ys_[seg];

        if (seg != cur_seg) {
            __syncthreads();
            const float4* Wg = (const float4*)Ws_[seg];
            #pragma unroll
            for (int j = 0; j < 8; j++) {
                int idx = tid + j * NT_THREADS;
                int row = idx >> 5, c4 = idx & 31;
                uint2 hi, lo;
                cvt_hi_lo(Wg[row * 32 + c4], hi, lo);
                *(uint2*)(smem + NWHI + row * XSTRIDE + c4 * 8) = hi;
                *(uint2*)(smem + NWLO + row * XSTRIDE + c4 * 8) = lo;
            }
            if (tid < 128) bs[tid] = bs_[seg][tid];
            cur_seg = seg;
        }

        CPA_WAIT0();
        __syncthreads();

        #pragma unroll
        for (int j = 0; j < 8; j++) {
            int idx = tid + j * NT_THREADS;
            int row = idx >> 5, c4 = idx & 31;
            uint2 hi, lo;
            cvt_hi_lo(rawv[idx], hi, lo);
            *(uint2*)(smem + NXHI + row * XSTRIDE + c4 * 8) = hi;
            *(uint2*)(smem + NXLO + row * XSTRIDE + c4 * 8) = lo;
        }
        __syncthreads();

        if (t + G < total) issue_copy(t + G);

        float acc[8][4];
        #pragma unroll
        for (int i = 0; i < 8; i++)
            #pragma unroll
            for (int j = 0; j < 4; j++) acc[i][j] = 0.f;

        #pragma unroll
        for (int k0 = 0; k0 < 128; k0 += 16) {
            uint32_t ah[4], al[4];
            uint32_t aaddr = sbase + NXHI + a_off + k0 * 2;
            LDSM4(ah, aaddr);
            LDSM4(al, aaddr + (NXLO - NXHI));
            #pragma unroll
            for (int c = 0; c < 4; c++) {
                uint32_t bh[4], bl[4];
                uint32_t baddr = sbase + NWHI + b_off + k0 * XSTRIDE + c * 32;
                LDSM4T(bh, baddr);
                LDSM4T(bl, baddr + (NWLO - NWHI));
                MMA16816(acc[2 * c],     ah, bh[0], bh[1]);
                MMA16816(acc[2 * c + 1], ah, bh[2], bh[3]);
                MMA16816(acc[2 * c],     ah, bl[0], bl[1]);
                MMA16816(acc[2 * c + 1], ah, bl[2], bl[3]);
                MMA16816(acc[2 * c],     al, bh[0], bh[1]);
                MMA16816(acc[2 * c + 1], al, bh[2], bh[3]);
            }
        }

        const int ra = row_base + r0 + (lane >> 2);
        const int rb = ra + 8;
        #pragma unroll
        for (int c8 = 0; c8 < 8; c8++) {
            int col = n0 + c8 * 8 + 2 * (lane & 3);
            float b0 = bs[col], b1 = bs[col + 1];
            if (ra < n) {
                float2 v = make_float2(acc[c8][0] + b0, acc[c8][1] + b1);
                *(float2*)(Y + (size_t)ra * 128 + col) = v;
            }
            if (rb < n) {
                float2 v = make_float2(acc[c8][2] + b0, acc[c8][3] + b1);
                *(float2*)(Y + (size_t)rb * 128 + col) = v;
            }
        }
    }
}

// ---------------------------------------------------------------------------
// Relation kernel v11: fully-async pipeline.
//   Tile = 128 edges x 128 cols, K=32, 512 threads / 16 warps, 1 block/SM.
//   Group A(t): raw Xe[t] + src/dst indices via cp.async (double-buffered).
//   Group B(t): XW[src] rows gathered into smem via cp.async (issued after
//   indices land, streams under the MMA).  A(t+G) issued alongside B(t).
//   wait_group 0 at tile top (A(t) done); wait_group 1 before epilogue
//   (B(t) done, A(t+G) still in flight; empty commit keeps counts aligned).
//   Epilogue: Tacc transpose (proven) + LDS XWg + relu + red.v4 — zero
//   exposed global latency.
// ---------------------------------------------------------------------------
#define RT_THREADS 512
#define RT_TILE 128
#define ASTR 80
#define TSTR 136
#define RB_HI 0
#define RB_LO 8704
#define RA_HI 17408
#define RA_LO 27648
#define RRAW  37888              // 2 x 16384
#define RXWG  70656              // 128 x 512 = 65536
#define RTACC 136192             // 128 x 136 x 4 = 69632
#define RSS   205824             // 2 x 512
#define RDS   206848             // 2 x 512
#define RT_SMEM 207872

__global__ __launch_bounds__(RT_THREADS, 1)
void rel_tc_kernel(const float* __restrict__ XW0, const float* __restrict__ Xe0,
                   const int* __restrict__ src0, const int* __restrict__ dst0,
                   const float* __restrict__ We0, float* __restrict__ out0,
                   const float* __restrict__ XW1, const float* __restrict__ Xe1,
                   const int* __restrict__ src1, const int* __restrict__ dst1,
                   const float* __restrict__ We1, float* __restrict__ out1,
                   int E)
{
    const float* XW = blockIdx.y ? XW1 : XW0;
    const float* Xe = blockIdx.y ? Xe1 : Xe0;
    const int*  src = blockIdx.y ? src1 : src0;
    const int*  dst = blockIdx.y ? dst1 : dst0;
    const float* We = blockIdx.y ? We1 : We0;
    float*      out = blockIdx.y ? out1 : out0;

    extern __shared__ char smem[];
    const uint32_t sbase = smem_u32(smem);
    float* Tacc = (float*)(smem + RTACC);
    const float* XWg = (const float*)(smem + RXWG);

    const int tid  = threadIdx.x;
    const int warp = tid >> 5;
    const int lane = tid & 31;
    const int r0 = (warp >> 1) * 16;
    const int n0 = (warp & 1) * 64;

    // Stage B = We (32 x 128) as bf16 hi/lo once per block.
    #pragma unroll
    for (int j = 0; j < 2; j++) {
        int idx = tid + j * RT_THREADS;
        int row = idx >> 5, c4 = idx & 31;
        uint2 hi, lo;
        cvt_hi_lo(((const float4*)We)[row * 32 + c4], hi, lo);
        *(uint2*)(smem + RB_HI + row * XSTRIDE + c4 * 8) = hi;
        *(uint2*)(smem + RB_LO + row * XSTRIDE + c4 * 8) = lo;
    }

    const uint32_t a_off = (uint32_t)((r0 + (lane & 15)) * ASTR + (lane >> 4) * 16);
    const int bg = lane >> 3;
    const uint32_t b_off = (uint32_t)(((lane & 7) + (bg & 1) * 8) * XSTRIDE
                                      + (n0 + (bg >> 1) * 8) * 2);

    const int ntiles = (E + RT_TILE - 1) / RT_TILE;
    const int G = gridDim.x;

    // Group A: raw Xe (1024 x 16B) + indices (256 x 4B) for tile tt -> buf.
    auto issue_A = [&](int tt, int buf) {
        int e0 = tt * RT_TILE;
        uint32_t rb = sbase + RRAW + buf * 16384;
        #pragma unroll
        for (int j = 0; j < 2; j++) {
            int idx = tid + j * RT_THREADS;
            int e = e0 + (idx >> 3);
            int ok = (e < E);
            const float* g = Xe + (size_t)(ok ? e : 0) * 32 + (idx & 7) * 4;
            CPA16(rb + idx * 16, g, ok ? 16 : 0);
        }
        if (tid < RT_TILE) {
            int e = e0 + tid;
            int ok = (e < E);
            CPA4(sbase + RSS + buf * 512 + tid * 4, src + (ok ? e : 0), ok ? 4 : 0);
        } else if (tid < 2 * RT_TILE) {
            int e = e0 + tid - RT_TILE;
            int ok = (e < E);
            CPA4(sbase + RDS + buf * 512 + (tid - RT_TILE) * 4,
                 dst + (ok ? e : 0), ok ? 4 : 0);
        }
        CPA_COMMIT();
    };

    // Group B: gather XW rows for tile in buf (4096 x 16B chunks).
    auto issue_B = [&](int buf) {
        const int* SsB = (const int*)(smem + RSS + buf * 512);
        #pragma unroll
        for (int j = 0; j < 8; j++) {
            int idx = tid + j * RT_THREADS;
            int el = idx >> 5, c = idx & 31;
            int s = SsB[el];
            const float* g = XW + (size_t)s * 128 + c * 4;
            CPA16(sbase + RXWG + idx * 16, g, 16);
        }
        CPA_COMMIT();
    };

    int t = blockIdx.x;
    int buf = 0;
    if (t < ntiles) issue_A(t, 0);
    __syncthreads();            // We staged (and before any wait)

    for (; t < ntiles; t += G) {
        const int e0 = t * RT_TILE;
        const float4* rawv = (const float4*)(smem + RRAW + buf * 16384);
        const int* Ds = (const int*)(smem + RDS + buf * 512);

        CPA_WAIT0();            // A(t): raw Xe + indices landed
        __syncthreads();

        // Convert raw Xe -> A hi/lo.
        #pragma unroll
        for (int j = 0; j < 2; j++) {
            int idx = tid + j * RT_THREADS;
            int row = idx >> 3, c4 = idx & 7;
            uint2 hi, lo;
            cvt_hi_lo(rawv[idx], hi, lo);
            *(uint2*)(smem + RA_HI + row * ASTR + c4 * 8) = hi;
            *(uint2*)(smem + RA_LO + row * ASTR + c4 * 8) = lo;
        }
        __syncthreads();        // A ready for ldmatrix; epilogue(t-G) fully done

        issue_B(buf);                                   // gather XW[t]
        if (t + G < ntiles) issue_A(t + G, buf ^ 1);    // next tile's raw+idx
        else CPA_COMMIT();                              // keep group count aligned

        float acc[8][4];
        #pragma unroll
        for (int i = 0; i < 8; i++)
            #pragma unroll
            for (int j = 0; j < 4; j++) acc[i][j] = 0.f;

        #pragma unroll
        for (int k0 = 0; k0 < 32; k0 += 16) {
            uint32_t ah[4], al[4];
            uint32_t aaddr = sbase + RA_HI + a_off + k0 * 2;
            LDSM4(ah, aaddr);
            LDSM4(al, aaddr + (RA_LO - RA_HI));
            #pragma unroll
            for (int c = 0; c < 4; c++) {
                uint32_t bh[4], bl[4];
                uint32_t baddr = sbase + RB_HI + b_off + k0 * XSTRIDE + c * 32;
                LDSM4T(bh, baddr);
                LDSM4T(bl, baddr + (RB_LO - RB_HI));
                MMA16816(acc[2 * c],     ah, bh[0], bh[1]);
                MMA16816(acc[2 * c + 1], ah, bh[2], bh[3]);
                MMA16816(acc[2 * c],     ah, bl[0], bl[1]);
                MMA16816(acc[2 * c + 1], ah, bl[2], bl[3]);
                MMA16816(acc[2 * c],     al, bh[0], bh[1]);
                MMA16816(acc[2 * c + 1], al, bh[2], bh[3]);
            }
        }

        // Transpose fragments into Tacc (row = edge-in-tile).
        {
            const int era = r0 + (lane >> 2);
            #pragma unroll
            for (int c8 = 0; c8 < 8; c8++) {
                int col = n0 + c8 * 8 + 2 * (lane & 3);
                *(float2*)(Tacc + era * TSTR + col) =
                    make_float2(acc[c8][0], acc[c8][1]);
                *(float2*)(Tacc + (era + 8) * TSTR + col) =
                    make_float2(acc[c8][2], acc[c8][3]);
            }
        }

        CPA_WAIT1();            // B(t) done (A(t+G) may still be in flight)
        __syncthreads();        // Tacc + XWg visible to all

        // Epilogue: warp owns 8 edges; all smem + red.v4 (coalesced 512B).
        #pragma unroll
        for (int i = 0; i < 8; i++) {
            int el = warp * 8 + i;
            int e = e0 + el;
            if (e < E) {
                int d = Ds[el];
                float4 v = *(float4*)(Tacc + el * TSTR + 4 * lane);
                float4 g = *(const float4*)(XWg + el * 128 + 4 * lane);
                v.x = fmaxf(v.x + g.x, 0.f);
                v.y = fmaxf(v.y + g.y, 0.f);
                v.z = fmaxf(v.z + g.z, 0.f);
                v.w = fmaxf(v.w + g.w, 0.f);
                red_add_v4(out + (size_t)d * 128 + 4 * lane, v);
            }
        }

        buf ^= 1;
    }
}

// ---------------------------------------------------------------------------
// kernel_launch (metadata order unchanged)
// ---------------------------------------------------------------------------
extern "C" void kernel_launch(void* const* d_in, const int* in_sizes, int n_in,
                              void* d_out, int out_size)
{
    const float* X_user   = (const float*)d_in[0];
    const float* X_item   = (const float*)d_in[1];
    const float* Xe_ui    = (const float*)d_in[2];
    const float* Xe_iu    = (const float*)d_in[3];
    const float* W_src_ui = (const float*)d_in[4];
    const float* W_edge_ui= (const float*)d_in[5];
    const float* b_ui     = (const float*)d_in[6];
    const float* W_src_iu = (const float*)d_in[7];
    const float* W_edge_iu= (const float*)d_in[8];
    const float* b_iu     = (const float*)d_in[9];
    const float* Wl_user  = (const float*)d_in[10];
    const float* bl_user  = (const float*)d_in[11];
    const float* Wl_item  = (const float*)d_in[12];
    const float* bl_item  = (const float*)d_in[13];
    const int*   src_ui   = (const int*)d_in[14];
    const int*   dst_ui   = (const int*)d_in[15];
    const int*   src_iu   = (const int*)d_in[16];
    const int*   dst_iu   = (const int*)d_in[17];

    const int n_user = in_sizes[0] / D_IN;
    const int n_item = in_sizes[1] / D_IN;
    const int E      = in_sizes[14];

    float* H_user = (float*)d_out;
    float* H_item = (float*)d_out + (size_t)n_user * D_OUT;

    void* p_xwu = nullptr; void* p_xwi = nullptr;
    cudaGetSymbolAddress(&p_xwu, g_xwu);
    cudaGetSymbolAddress(&p_xwi, g_xwi);
    float* xwu = (float*)p_xwu;
    float* xwi = (float*)p_xwi;

    cudaFuncSetAttribute(node_tc_kernel,
                         cudaFuncAttributeMaxDynamicSharedMemorySize,
                         NT_SMEM);
    cudaFuncSetAttribute(rel_tc_kernel,
                         cudaFuncAttributeMaxDynamicSharedMemorySize,
                         RT_SMEM);

    node_tc_kernel<<<148, NT_THREADS, NT_SMEM>>>(
        X_user, X_item,
        W_src_ui, b_ui, xwu,
        Wl_user, bl_user, H_user,
        W_src_iu, b_iu, xwi,
        Wl_item, bl_item, H_item,
        n_user, n_item);

    dim3 grel(74, 2);   // 148 blocks, 1/SM (208KB smem each)
    rel_tc_kernel<<<grel, RT_THREADS, RT_SMEM>>>(
        xwu, Xe_ui, src_ui, dst_ui, W_edge_ui, H_item,
        xwi, Xe_iu, src_iu, dst_iu, W_edge_iu, H_user,
        E);
}

// round 14
// speedup vs baseline: 1.7949x; 1.0418x over previous
#include <cuda_runtime.h>
#include <cuda_bf16.h>
#include <cstdint>
#include <cstddef>

#define D_IN   128
#define D_OUT  128
#define D_EDGE 32
#define MAX_NODES 100000

__device__ float g_xwu[(size_t)MAX_NODES * D_OUT];
__device__ float g_xwi[(size_t)MAX_NODES * D_OUT];

// ============================= common helpers ==============================
__device__ __forceinline__ uint32_t smem_u32(const void* p) {
    uint32_t a;
    asm("{ .reg .u64 t; cvta.to.shared.u64 t, %1; cvt.u32.u64 %0, t; }"
        : "=r"(a) : "l"(p));
    return a;
}
__device__ __forceinline__ uint32_t bf2bits(__nv_bfloat162 h) {
    return *reinterpret_cast<uint32_t*>(&h);
}
__device__ __forceinline__ void cvt_hi_lo(float4 x, uint2& hi, uint2& lo) {
    __nv_bfloat162 h01 = __floats2bfloat162_rn(x.x, x.y);
    __nv_bfloat162 h23 = __floats2bfloat162_rn(x.z, x.w);
    float2 f01 = __bfloat1622float2(h01);
    float2 f23 = __bfloat1622float2(h23);
    __nv_bfloat162 l01 = __floats2bfloat162_rn(x.x - f01.x, x.y - f01.y);
    __nv_bfloat162 l23 = __floats2bfloat162_rn(x.z - f23.x, x.w - f23.y);
    hi = make_uint2(bf2bits(h01), bf2bits(h23));
    lo = make_uint2(bf2bits(l01), bf2bits(l23));
}

#define LDSM4(r, addr) \
    asm volatile("ldmatrix.sync.aligned.m8n8.x4.shared.b16 {%0,%1,%2,%3}, [%4];" \
        : "=r"((r)[0]), "=r"((r)[1]), "=r"((r)[2]), "=r"((r)[3]) : "r"(addr))
#define LDSM4T(r, addr) \
    asm volatile("ldmatrix.sync.aligned.m8n8.x4.trans.shared.b16 {%0,%1,%2,%3}, [%4];" \
        : "=r"((r)[0]), "=r"((r)[1]), "=r"((r)[2]), "=r"((r)[3]) : "r"(addr))
#define MMA16816(c, a, b0_, b1_) \
    asm volatile("mma.sync.aligned.m16n8k16.row.col.f32.bf16.bf16.f32 " \
        "{%0,%1,%2,%3}, {%4,%5,%6,%7}, {%8,%9}, {%0,%1,%2,%3};" \
        : "+f"((c)[0]), "+f"((c)[1]), "+f"((c)[2]), "+f"((c)[3]) \
        : "r"((a)[0]), "r"((a)[1]), "r"((a)[2]), "r"((a)[3]), "r"(b0_), "r"(b1_))

#define CPA16(s, g, sz) \
    asm volatile("cp.async.cg.shared.global [%0], [%1], 16, %2;" \
                 :: "r"(s), "l"(g), "r"(sz) : "memory")
#define CPA4(s, g, sz) \
    asm volatile("cp.async.ca.shared.global [%0], [%1], 4, %2;" \
                 :: "r"(s), "l"(g), "r"(sz) : "memory")
#define CPA_COMMIT() asm volatile("cp.async.commit_group;" ::: "memory")
#define CPA_WAIT0()  asm volatile("cp.async.wait_group 0;" ::: "memory")
#define CPA_WAIT1()  asm volatile("cp.async.wait_group 1;" ::: "memory")

__device__ __forceinline__ void red_add_v4(float* p, float4 v) {
    asm volatile("red.global.add.v4.f32 [%0], {%1,%2,%3,%4};"
                 :: "l"(p), "f"(v.x), "f"(v.y), "f"(v.z), "f"(v.w)
                 : "memory");
}

// ---------------------------------------------------------------------------
// Node stage v3: FUSED dual-GEMM per X tile.
//   64-row tiles; all 4 weight matrices (hi/lo) staged per segment; X read
//   from DRAM and converted ONCE, A-fragments shared by both GEMMs in a
//   fused k-loop. 512 threads / 16 warps: warp w -> rows (w>>2)*16..+15,
//   cols (w&3)*32..+31. cp.async double-buffers the next raw X tile.
// ---------------------------------------------------------------------------
#define NT_THREADS 512
#define NTROWS 64
#define XSTRIDE 272
#define W1HI 0
#define W1LO 34816
#define W2HI 69632
#define W2LO 104448
#define NXHI 139264
#define NXLO 156672
#define NRAW 174080
#define NBS  206848
#define NT_SMEM (206848 + 1024)

__global__ __launch_bounds__(NT_THREADS, 1)
void node_tc_kernel(const float* __restrict__ Xu, const float* __restrict__ Xi,
                    const float* __restrict__ Wsu, const float* __restrict__ bu,
                    float* __restrict__ xwu,
                    const float* __restrict__ Wlu, const float* __restrict__ blu,
                    float* __restrict__ Hu,
                    const float* __restrict__ Wsi, const float* __restrict__ bi,
                    float* __restrict__ xwi,
                    const float* __restrict__ Wli, const float* __restrict__ bli,
                    float* __restrict__ Hi,
                    int nu, int ni)
{
    extern __shared__ char smem[];
    const uint32_t sbase = smem_u32(smem);
    float* bs = (float*)(smem + NBS);           // [0:128) b1, [128:256) b2
    const float4* rawv = (const float4*)(smem + NRAW);

    const int tid  = threadIdx.x;
    const int warp = tid >> 5;
    const int lane = tid & 31;
    const int r0 = (warp >> 2) * 16;            // 4 row groups
    const int n0 = (warp & 3) * 32;             // 4 col groups

    const float* Xseg[2]  = {Xu, Xi};
    const float* W1seg[2] = {Wsu, Wsi};
    const float* W2seg[2] = {Wlu, Wli};
    const float* b1seg[2] = {bu, bi};
    const float* b2seg[2] = {blu, bli};
    float* Y1seg[2] = {xwu, xwi};
    float* Y2seg[2] = {Hu, Hi};
    const int nseg[2] = {nu, ni};

    const int tu = (nu + NTROWS - 1) / NTROWS;
    const int ti = (ni + NTROWS - 1) / NTROWS;
    const int total = tu + ti;
    const int G = gridDim.x;

    const uint32_t a_off = (uint32_t)((r0 + (lane & 15)) * XSTRIDE + (lane >> 4) * 16);
    const int bg = lane >> 3;
    const uint32_t b_off = (uint32_t)(((lane & 7) + (bg & 1) * 8) * XSTRIDE
                                      + (n0 + (bg >> 1) * 8) * 2);

    auto issue_copy = [&](int tt) {
        int seg = (tt >= tu);
        const float* Xg = Xseg[seg];
        const int n = nseg[seg];
        const int row_base = (tt - (seg ? tu : 0)) * NTROWS;
        #pragma unroll
        for (int j = 0; j < 4; j++) {
            int idx = tid + j * NT_THREADS;     // 2048 float4 chunks
            int row = idx >> 5, c4 = idx & 31;
            int grow = row_base + row;
            int ok = (grow < n);
            const float* src = Xg + (size_t)(ok ? grow : 0) * 128 + c4 * 4;
            CPA16(sbase + NRAW + idx * 16, src, ok ? 16 : 0);
        }
        CPA_COMMIT();
    };

    int cur_seg = -1;
    int t = blockIdx.x;
    if (t < total) issue_copy(t);

    for (; t < total; t += G) {
        int seg = (t >= tu);
        const int n = nseg[seg];
        const int row_base = (t - (seg ? tu : 0)) * NTROWS;

        if (seg != cur_seg) {
            __syncthreads();
            const float4* W1g = (const float4*)W1seg[seg];
            const float4* W2g = (const float4*)W2seg[seg];
            #pragma unroll
            for (int j = 0; j < 8; j++) {
                int idx = tid + j * NT_THREADS;  // 4096 chunks per matrix
                int row = idx >> 5, c4 = idx & 31;
                uint2 hi, lo;
                cvt_hi_lo(W1g[row * 32 + c4], hi, lo);
                *(uint2*)(smem + W1HI + row * XSTRIDE + c4 * 8) = hi;
                *(uint2*)(smem + W1LO + row * XSTRIDE + c4 * 8) = lo;
                cvt_hi_lo(W2g[row * 32 + c4], hi, lo);
                *(uint2*)(smem + W2HI + row * XSTRIDE + c4 * 8) = hi;
                *(uint2*)(smem + W2LO + row * XSTRIDE + c4 * 8) = lo;
            }
            if (tid < 128) bs[tid] = b1seg[seg][tid];
            else if (tid < 256) bs[tid] = b2seg[seg][tid - 128];
            cur_seg = seg;
        }

        CPA_WAIT0();
        __syncthreads();

        // Convert raw X -> bf16 hi/lo (once; shared by both GEMMs).
        #pragma unroll
        for (int j = 0; j < 4; j++) {
            int idx = tid + j * NT_THREADS;
            int row = idx >> 5, c4 = idx & 31;
            uint2 hi, lo;
            cvt_hi_lo(rawv[idx], hi, lo);
            *(uint2*)(smem + NXHI + row * XSTRIDE + c4 * 8) = hi;
            *(uint2*)(smem + NXLO + row * XSTRIDE + c4 * 8) = lo;
        }
        __syncthreads();

        if (t + G < total) issue_copy(t + G);

        float acc1[4][4], acc2[4][4];
        #pragma unroll
        for (int i = 0; i < 4; i++)
            #pragma unroll
            for (int j = 0; j < 4; j++) { acc1[i][j] = 0.f; acc2[i][j] = 0.f; }

        #pragma unroll
        for (int k0 = 0; k0 < 128; k0 += 16) {
            uint32_t ah[4], al[4];
            uint32_t aaddr = sbase + NXHI + a_off + k0 * 2;
            LDSM4(ah, aaddr);
            LDSM4(al, aaddr + (NXLO - NXHI));
            #pragma unroll
            for (int c = 0; c < 2; c++) {
                uint32_t bh[4], bl[4];
                uint32_t b1addr = sbase + W1HI + b_off + k0 * XSTRIDE + c * 32;
                LDSM4T(bh, b1addr);
                LDSM4T(bl, b1addr + (W1LO - W1HI));
                MMA16816(acc1[2 * c],     ah, bh[0], bh[1]);
                MMA16816(acc1[2 * c + 1], ah, bh[2], bh[3]);
                MMA16816(acc1[2 * c],     ah, bl[0], bl[1]);
                MMA16816(acc1[2 * c + 1], ah, bl[2], bl[3]);
                MMA16816(acc1[2 * c],     al, bh[0], bh[1]);
                MMA16816(acc1[2 * c + 1], al, bh[2], bh[3]);

                uint32_t b2addr = sbase + W2HI + b_off + k0 * XSTRIDE + c * 32;
                LDSM4T(bh, b2addr);
                LDSM4T(bl, b2addr + (W2LO - W2HI));
                MMA16816(acc2[2 * c],     ah, bh[0], bh[1]);
                MMA16816(acc2[2 * c + 1], ah, bh[2], bh[3]);
                MMA16816(acc2[2 * c],     ah, bl[0], bl[1]);
                MMA16816(acc2[2 * c + 1], ah, bl[2], bl[3]);
                MMA16816(acc2[2 * c],     al, bh[0], bh[1]);
                MMA16816(acc2[2 * c + 1], al, bh[2], bh[3]);
            }
        }

        // Store both outputs (+bias).
        float* Y1 = Y1seg[seg];
        float* Y2 = Y2seg[seg];
        const int ra = row_base + r0 + (lane >> 2);
        const int rb = ra + 8;
        #pragma unroll
        for (int c8 = 0; c8 < 4; c8++) {
            int col = n0 + c8 * 8 + 2 * (lane & 3);
            float b10 = bs[col], b11 = bs[col + 1];
            float b20 = bs[128 + col], b21 = bs[128 + col + 1];
            if (ra < n) {
                *(float2*)(Y1 + (size_t)ra * 128 + col) =
                    make_float2(acc1[c8][0] + b10, acc1[c8][1] + b11);
                *(float2*)(Y2 + (size_t)ra * 128 + col) =
                    make_float2(acc2[c8][0] + b20, acc2[c8][1] + b21);
            }
            if (rb < n) {
                *(float2*)(Y1 + (size_t)rb * 128 + col) =
                    make_float2(acc1[c8][2] + b10, acc1[c8][3] + b11);
                *(float2*)(Y2 + (size_t)rb * 128 + col) =
                    make_float2(acc2[c8][2] + b20, acc2[c8][3] + b21);
            }
        }
    }
}

// ---------------------------------------------------------------------------
// Relation kernel (R13 pipeline, single relation per launch — relations run
// SEQUENTIALLY so each phase's hot set (XW 51MB + out 51MB) fits L2).
// ---------------------------------------------------------------------------
#define RT_THREADS 512
#define RT_TILE 128
#define ASTR 80
#define TSTR 136
#define RB_HI 0
#define RB_LO 8704
#define RA_HI 17408
#define RA_LO 27648
#define RRAW  37888              // 2 x 16384
#define RXWG  70656              // 65536
#define RTACC 136192             // 69632
#define RSS   205824             // 2 x 512
#define RDS   206848             // 2 x 512
#define RT_SMEM 207872

__global__ __launch_bounds__(RT_THREADS, 1)
void rel_tc_kernel(const float* __restrict__ XW,
                   const float* __restrict__ Xe,
                   const int* __restrict__ src,
                   const int* __restrict__ dst,
                   const float* __restrict__ We,
                   float* __restrict__ out,
                   int E)
{
    extern __shared__ char smem[];
    const uint32_t sbase = smem_u32(smem);
    float* Tacc = (float*)(smem + RTACC);
    const float* XWg = (const float*)(smem + RXWG);

    const int tid  = threadIdx.x;
    const int warp = tid >> 5;
    const int lane = tid & 31;
    const int r0 = (warp >> 1) * 16;
    const int n0 = (warp & 1) * 64;

    #pragma unroll
    for (int j = 0; j < 2; j++) {
        int idx = tid + j * RT_THREADS;
        int row = idx >> 5, c4 = idx & 31;
        uint2 hi, lo;
        cvt_hi_lo(((const float4*)We)[row * 32 + c4], hi, lo);
        *(uint2*)(smem + RB_HI + row * XSTRIDE + c4 * 8) = hi;
        *(uint2*)(smem + RB_LO + row * XSTRIDE + c4 * 8) = lo;
    }

    const uint32_t a_off = (uint32_t)((r0 + (lane & 15)) * ASTR + (lane >> 4) * 16);
    const int bg = lane >> 3;
    const uint32_t b_off = (uint32_t)(((lane & 7) + (bg & 1) * 8) * XSTRIDE
                                      + (n0 + (bg >> 1) * 8) * 2);

    const int ntiles = (E + RT_TILE - 1) / RT_TILE;
    const int G = gridDim.x;

    auto issue_A = [&](int tt, int buf) {
        int e0 = tt * RT_TILE;
        uint32_t rb = sbase + RRAW + buf * 16384;
        #pragma unroll
        for (int j = 0; j < 2; j++) {
            int idx = tid + j * RT_THREADS;
            int e = e0 + (idx >> 3);
            int ok = (e < E);
            const float* g = Xe + (size_t)(ok ? e : 0) * 32 + (idx & 7) * 4;
            CPA16(rb + idx * 16, g, ok ? 16 : 0);
        }
        if (tid < RT_TILE) {
            int e = e0 + tid;
            int ok = (e < E);
            CPA4(sbase + RSS + buf * 512 + tid * 4, src + (ok ? e : 0), ok ? 4 : 0);
        } else if (tid < 2 * RT_TILE) {
            int e = e0 + tid - RT_TILE;
            int ok = (e < E);
            CPA4(sbase + RDS + buf * 512 + (tid - RT_TILE) * 4,
                 dst + (ok ? e : 0), ok ? 4 : 0);
        }
        CPA_COMMIT();
    };

    auto issue_B = [&](int buf) {
        const int* SsB = (const int*)(smem + RSS + buf * 512);
        #pragma unroll
        for (int j = 0; j < 8; j++) {
            int idx = tid + j * RT_THREADS;
            int el = idx >> 5, c = idx & 31;
            int s = SsB[el];
            const float* g = XW + (size_t)s * 128 + c * 4;
            CPA16(sbase + RXWG + idx * 16, g, 16);
        }
        CPA_COMMIT();
    };

    int t = blockIdx.x;
    int buf = 0;
    if (t < ntiles) issue_A(t, 0);
    __syncthreads();

    for (; t < ntiles; t += G) {
        const int e0 = t * RT_TILE;
        const float4* rawv = (const float4*)(smem + RRAW + buf * 16384);
        const int* Ds = (const int*)(smem + RDS + buf * 512);

        CPA_WAIT0();
        __syncthreads();

        #pragma unroll
        for (int j = 0; j < 2; j++) {
            int idx = tid + j * RT_THREADS;
            int row = idx >> 3, c4 = idx & 7;
            uint2 hi, lo;
            cvt_hi_lo(rawv[idx], hi, lo);
            *(uint2*)(smem + RA_HI + row * ASTR + c4 * 8) = hi;
            *(uint2*)(smem + RA_LO + row * ASTR + c4 * 8) = lo;
        }
        __syncthreads();

        issue_B(buf);
        if (t + G < ntiles) issue_A(t + G, buf ^ 1);
        else CPA_COMMIT();

        float acc[8][4];
        #pragma unroll
        for (int i = 0; i < 8; i++)
            #pragma unroll
            for (int j = 0; j < 4; j++) acc[i][j] = 0.f;

        #pragma unroll
        for (int k0 = 0; k0 < 32; k0 += 16) {
            uint32_t ah[4], al[4];
            uint32_t aaddr = sbase + RA_HI + a_off + k0 * 2;
            LDSM4(ah, aaddr);
            LDSM4(al, aaddr + (RA_LO - RA_HI));
            #pragma unroll
            for (int c = 0; c < 4; c++) {
                uint32_t bh[4], bl[4];
                uint32_t baddr = sbase + RB_HI + b_off + k0 * XSTRIDE + c * 32;
                LDSM4T(bh, baddr);
                LDSM4T(bl, baddr + (RB_LO - RB_HI));
                MMA16816(acc[2 * c],     ah, bh[0], bh[1]);
                MMA16816(acc[2 * c + 1], ah, bh[2], bh[3]);
                MMA16816(acc[2 * c],     ah, bl[0], bl[1]);
                MMA16816(acc[2 * c + 1], ah, bl[2], bl[3]);
                MMA16816(acc[2 * c],     al, bh[0], bh[1]);
                MMA16816(acc[2 * c + 1], al, bh[2], bh[3]);
            }
        }

        {
            const int era = r0 + (lane >> 2);
            #pragma unroll
            for (int c8 = 0; c8 < 8; c8++) {
                int col = n0 + c8 * 8 + 2 * (lane & 3);
                *(float2*)(Tacc + era * TSTR + col) =
                    make_float2(acc[c8][0], acc[c8][1]);
                *(float2*)(Tacc + (era + 8) * TSTR + col) =
                    make_float2(acc[c8][2], acc[c8][3]);
            }
        }

        CPA_WAIT1();
        __syncthreads();

        #pragma unroll
        for (int i = 0; i < 8; i++) {
            int el = warp * 8 + i;
            int e = e0 + el;
            if (e < E) {
                int d = Ds[el];
                float4 v = *(float4*)(Tacc + el * TSTR + 4 * lane);
                float4 g = *(const float4*)(XWg + el * 128 + 4 * lane);
                v.x = fmaxf(v.x + g.x, 0.f);
                v.y = fmaxf(v.y + g.y, 0.f);
                v.z = fmaxf(v.z + g.z, 0.f);
                v.w = fmaxf(v.w + g.w, 0.f);
                red_add_v4(out + (size_t)d * 128 + 4 * lane, v);
            }
        }

        buf ^= 1;
    }
}

// ---------------------------------------------------------------------------
// kernel_launch (metadata order unchanged)
// ---------------------------------------------------------------------------
extern "C" void kernel_launch(void* const* d_in, const int* in_sizes, int n_in,
                              void* d_out, int out_size)
{
    const float* X_user   = (const float*)d_in[0];
    const float* X_item   = (const float*)d_in[1];
    const float* Xe_ui    = (const float*)d_in[2];
    const float* Xe_iu    = (const float*)d_in[3];
    const float* W_src_ui = (const float*)d_in[4];
    const float* W_edge_ui= (const float*)d_in[5];
    const float* b_ui     = (const float*)d_in[6];
    const float* W_src_iu = (const float*)d_in[7];
    const float* W_edge_iu= (const float*)d_in[8];
    const float* b_iu     = (const float*)d_in[9];
    const float* Wl_user  = (const float*)d_in[10];
    const float* bl_user  = (const float*)d_in[11];
    const float* Wl_item  = (const float*)d_in[12];
    const float* bl_item  = (const float*)d_in[13];
    const int*   src_ui   = (const int*)d_in[14];
    const int*   dst_ui   = (const int*)d_in[15];
    const int*   src_iu   = (const int*)d_in[16];
    const int*   dst_iu   = (const int*)d_in[17];

    const int n_user = in_sizes[0] / D_IN;
    const int n_item = in_sizes[1] / D_IN;
    const int E      = in_sizes[14];

    float* H_user = (float*)d_out;
    float* H_item = (float*)d_out + (size_t)n_user * D_OUT;

    void* p_xwu = nullptr; void* p_xwi = nullptr;
    cudaGetSymbolAddress(&p_xwu, g_xwu);
    cudaGetSymbolAddress(&p_xwi, g_xwi);
    float* xwu = (float*)p_xwu;
    float* xwi = (float*)p_xwi;

    cudaFuncSetAttribute(node_tc_kernel,
                         cudaFuncAttributeMaxDynamicSharedMemorySize,
                         NT_SMEM);
    cudaFuncSetAttribute(rel_tc_kernel,
                         cudaFuncAttributeMaxDynamicSharedMemorySize,
                         RT_SMEM);

    node_tc_kernel<<<148, NT_THREADS, NT_SMEM>>>(
        X_user, X_item,
        W_src_ui, b_ui, xwu,
        Wl_user, bl_user, H_user,
        W_src_iu, b_iu, xwi,
        Wl_item, bl_item, H_item,
        n_user, n_item);

    // Sequential relations: each phase's hot set (XW + out = 102MB) ~ fits L2.
    rel_tc_kernel<<<148, RT_THREADS, RT_SMEM>>>(
        xwu, Xe_ui, src_ui, dst_ui, W_edge_ui, H_item, E);
    rel_tc_kernel<<<148, RT_THREADS, RT_SMEM>>>(
        xwi, Xe_iu, src_iu, dst_iu, W_edge_iu, H_user, E);
}

// round 15
// speedup vs baseline: 1.9022x; 1.0598x over previous
#include <cuda_runtime.h>
#include <cuda_bf16.h>
#include <cstdint>
#include <cstddef>

#define D_IN   128
#define D_OUT  128
#define D_EDGE 32
#define MAX_NODES 100000

__device__ float g_xwu[(size_t)MAX_NODES * D_OUT];
__device__ float g_xwi[(size_t)MAX_NODES * D_OUT];

// ============================= common helpers ==============================
__device__ __forceinline__ uint32_t smem_u32(const void* p) {
    uint32_t a;
    asm("{ .reg .u64 t; cvta.to.shared.u64 t, %1; cvt.u32.u64 %0, t; }"
        : "=r"(a) : "l"(p));
    return a;
}
__device__ __forceinline__ uint32_t bf2bits(__nv_bfloat162 h) {
    return *reinterpret_cast<uint32_t*>(&h);
}
__device__ __forceinline__ void cvt_hi_lo(float4 x, uint2& hi, uint2& lo) {
    __nv_bfloat162 h01 = __floats2bfloat162_rn(x.x, x.y);
    __nv_bfloat162 h23 = __floats2bfloat162_rn(x.z, x.w);
    float2 f01 = __bfloat1622float2(h01);
    float2 f23 = __bfloat1622float2(h23);
    __nv_bfloat162 l01 = __floats2bfloat162_rn(x.x - f01.x, x.y - f01.y);
    __nv_bfloat162 l23 = __floats2bfloat162_rn(x.z - f23.x, x.w - f23.y);
    hi = make_uint2(bf2bits(h01), bf2bits(h23));
    lo = make_uint2(bf2bits(l01), bf2bits(l23));
}

#define LDSM4(r, addr) \
    asm volatile("ldmatrix.sync.aligned.m8n8.x4.shared.b16 {%0,%1,%2,%3}, [%4];" \
        : "=r"((r)[0]), "=r"((r)[1]), "=r"((r)[2]), "=r"((r)[3]) : "r"(addr))
#define LDSM4T(r, addr) \
    asm volatile("ldmatrix.sync.aligned.m8n8.x4.trans.shared.b16 {%0,%1,%2,%3}, [%4];" \
        : "=r"((r)[0]), "=r"((r)[1]), "=r"((r)[2]), "=r"((r)[3]) : "r"(addr))
#define MMA16816(c, a, b0_, b1_) \
    asm volatile("mma.sync.aligned.m16n8k16.row.col.f32.bf16.bf16.f32 " \
        "{%0,%1,%2,%3}, {%4,%5,%6,%7}, {%8,%9}, {%0,%1,%2,%3};" \
        : "+f"((c)[0]), "+f"((c)[1]), "+f"((c)[2]), "+f"((c)[3]) \
        : "r"((a)[0]), "r"((a)[1]), "r"((a)[2]), "r"((a)[3]), "r"(b0_), "r"(b1_))

#define CPA16(s, g, sz) \
    asm volatile("cp.async.cg.shared.global [%0], [%1], 16, %2;" \
                 :: "r"(s), "l"(g), "r"(sz) : "memory")
#define CPA4(s, g, sz) \
    asm volatile("cp.async.ca.shared.global [%0], [%1], 4, %2;" \
                 :: "r"(s), "l"(g), "r"(sz) : "memory")
#define CPA_COMMIT() asm volatile("cp.async.commit_group;" ::: "memory")
#define CPA_WAIT0()  asm volatile("cp.async.wait_group 0;" ::: "memory")
#define CPA_WAIT1()  asm volatile("cp.async.wait_group 1;" ::: "memory")

__device__ __forceinline__ void red_add_v4(float* p, float4 v) {
    asm volatile("red.global.add.v4.f32 [%0], {%1,%2,%3,%4};"
                 :: "l"(p), "f"(v.x), "f"(v.y), "f"(v.z), "f"(v.w)
                 : "memory");
}

// ---------------------------------------------------------------------------
// Node stage (R14, unchanged): fused dual-GEMM per X tile, cp.async pipelined.
// ---------------------------------------------------------------------------
#define NT_THREADS 512
#define NTROWS 64
#define XSTRIDE 272
#define W1HI 0
#define W1LO 34816
#define W2HI 69632
#define W2LO 104448
#define NXHI 139264
#define NXLO 156672
#define NRAW 174080
#define NBS  206848
#define NT_SMEM (206848 + 1024)

__global__ __launch_bounds__(NT_THREADS, 1)
void node_tc_kernel(const float* __restrict__ Xu, const float* __restrict__ Xi,
                    const float* __restrict__ Wsu, const float* __restrict__ bu,
                    float* __restrict__ xwu,
                    const float* __restrict__ Wlu, const float* __restrict__ blu,
                    float* __restrict__ Hu,
                    const float* __restrict__ Wsi, const float* __restrict__ bi,
                    float* __restrict__ xwi,
                    const float* __restrict__ Wli, const float* __restrict__ bli,
                    float* __restrict__ Hi,
                    int nu, int ni)
{
    extern __shared__ char smem[];
    const uint32_t sbase = smem_u32(smem);
    float* bs = (float*)(smem + NBS);
    const float4* rawv = (const float4*)(smem + NRAW);

    const int tid  = threadIdx.x;
    const int warp = tid >> 5;
    const int lane = tid & 31;
    const int r0 = (warp >> 2) * 16;
    const int n0 = (warp & 3) * 32;

    const float* Xseg[2]  = {Xu, Xi};
    const float* W1seg[2] = {Wsu, Wsi};
    const float* W2seg[2] = {Wlu, Wli};
    const float* b1seg[2] = {bu, bi};
    const float* b2seg[2] = {blu, bli};
    float* Y1seg[2] = {xwu, xwi};
    float* Y2seg[2] = {Hu, Hi};
    const int nseg[2] = {nu, ni};

    const int tu = (nu + NTROWS - 1) / NTROWS;
    const int ti = (ni + NTROWS - 1) / NTROWS;
    const int total = tu + ti;
    const int G = gridDim.x;

    const uint32_t a_off = (uint32_t)((r0 + (lane & 15)) * XSTRIDE + (lane >> 4) * 16);
    const int bg = lane >> 3;
    const uint32_t b_off = (uint32_t)(((lane & 7) + (bg & 1) * 8) * XSTRIDE
                                      + (n0 + (bg >> 1) * 8) * 2);

    auto issue_copy = [&](int tt) {
        int seg = (tt >= tu);
        const float* Xg = Xseg[seg];
        const int n = nseg[seg];
        const int row_base = (tt - (seg ? tu : 0)) * NTROWS;
        #pragma unroll
        for (int j = 0; j < 4; j++) {
            int idx = tid + j * NT_THREADS;
            int row = idx >> 5, c4 = idx & 31;
            int grow = row_base + row;
            int ok = (grow < n);
            const float* src = Xg + (size_t)(ok ? grow : 0) * 128 + c4 * 4;
            CPA16(sbase + NRAW + idx * 16, src, ok ? 16 : 0);
        }
        CPA_COMMIT();
    };

    int cur_seg = -1;
    int t = blockIdx.x;
    if (t < total) issue_copy(t);

    for (; t < total; t += G) {
        int seg = (t >= tu);
        const int n = nseg[seg];
        const int row_base = (t - (seg ? tu : 0)) * NTROWS;

        if (seg != cur_seg) {
            __syncthreads();
            const float4* W1g = (const float4*)W1seg[seg];
            const float4* W2g = (const float4*)W2seg[seg];
            #pragma unroll
            for (int j = 0; j < 8; j++) {
                int idx = tid + j * NT_THREADS;
                int row = idx >> 5, c4 = idx & 31;
                uint2 hi, lo;
                cvt_hi_lo(W1g[row * 32 + c4], hi, lo);
                *(uint2*)(smem + W1HI + row * XSTRIDE + c4 * 8) = hi;
                *(uint2*)(smem + W1LO + row * XSTRIDE + c4 * 8) = lo;
                cvt_hi_lo(W2g[row * 32 + c4], hi, lo);
                *(uint2*)(smem + W2HI + row * XSTRIDE + c4 * 8) = hi;
                *(uint2*)(smem + W2LO + row * XSTRIDE + c4 * 8) = lo;
            }
            if (tid < 128) bs[tid] = b1seg[seg][tid];
            else if (tid < 256) bs[tid] = b2seg[seg][tid - 128];
            cur_seg = seg;
        }

        CPA_WAIT0();
        __syncthreads();

        #pragma unroll
        for (int j = 0; j < 4; j++) {
            int idx = tid + j * NT_THREADS;
            int row = idx >> 5, c4 = idx & 31;
            uint2 hi, lo;
            cvt_hi_lo(rawv[idx], hi, lo);
            *(uint2*)(smem + NXHI + row * XSTRIDE + c4 * 8) = hi;
            *(uint2*)(smem + NXLO + row * XSTRIDE + c4 * 8) = lo;
        }
        __syncthreads();

        if (t + G < total) issue_copy(t + G);

        float acc1[4][4], acc2[4][4];
        #pragma unroll
        for (int i = 0; i < 4; i++)
            #pragma unroll
            for (int j = 0; j < 4; j++) { acc1[i][j] = 0.f; acc2[i][j] = 0.f; }

        #pragma unroll
        for (int k0 = 0; k0 < 128; k0 += 16) {
            uint32_t ah[4], al[4];
            uint32_t aaddr = sbase + NXHI + a_off + k0 * 2;
            LDSM4(ah, aaddr);
            LDSM4(al, aaddr + (NXLO - NXHI));
            #pragma unroll
            for (int c = 0; c < 2; c++) {
                uint32_t bh[4], bl[4];
                uint32_t b1addr = sbase + W1HI + b_off + k0 * XSTRIDE + c * 32;
                LDSM4T(bh, b1addr);
                LDSM4T(bl, b1addr + (W1LO - W1HI));
                MMA16816(acc1[2 * c],     ah, bh[0], bh[1]);
                MMA16816(acc1[2 * c + 1], ah, bh[2], bh[3]);
                MMA16816(acc1[2 * c],     ah, bl[0], bl[1]);
                MMA16816(acc1[2 * c + 1], ah, bl[2], bl[3]);
                MMA16816(acc1[2 * c],     al, bh[0], bh[1]);
                MMA16816(acc1[2 * c + 1], al, bh[2], bh[3]);

                uint32_t b2addr = sbase + W2HI + b_off + k0 * XSTRIDE + c * 32;
                LDSM4T(bh, b2addr);
                LDSM4T(bl, b2addr + (W2LO - W2HI));
                MMA16816(acc2[2 * c],     ah, bh[0], bh[1]);
                MMA16816(acc2[2 * c + 1], ah, bh[2], bh[3]);
                MMA16816(acc2[2 * c],     ah, bl[0], bl[1]);
                MMA16816(acc2[2 * c + 1], ah, bl[2], bl[3]);
                MMA16816(acc2[2 * c],     al, bh[0], bh[1]);
                MMA16816(acc2[2 * c + 1], al, bh[2], bh[3]);
            }
        }

        float* Y1 = Y1seg[seg];
        float* Y2 = Y2seg[seg];
        const int ra = row_base + r0 + (lane >> 2);
        const int rb = ra + 8;
        #pragma unroll
        for (int c8 = 0; c8 < 4; c8++) {
            int col = n0 + c8 * 8 + 2 * (lane & 3);
            float b10 = bs[col], b11 = bs[col + 1];
            float b20 = bs[128 + col], b21 = bs[128 + col + 1];
            if (ra < n) {
                *(float2*)(Y1 + (size_t)ra * 128 + col) =
                    make_float2(acc1[c8][0] + b10, acc1[c8][1] + b11);
                *(float2*)(Y2 + (size_t)ra * 128 + col) =
                    make_float2(acc2[c8][0] + b20, acc2[c8][1] + b21);
            }
            if (rb < n) {
                *(float2*)(Y1 + (size_t)rb * 128 + col) =
                    make_float2(acc1[c8][2] + b10, acc1[c8][3] + b11);
                *(float2*)(Y2 + (size_t)rb * 128 + col) =
                    make_float2(acc2[c8][2] + b20, acc2[c8][3] + b21);
            }
        }
    }
}

// ---------------------------------------------------------------------------
// Relation kernel v12: R13 async pipeline at 64-edge tiles / 256 threads so
// TWO blocks co-reside per SM (110KB smem each) — one block issues while the
// other sits at its pipeline wait, hiding the sync/wait chain.
// Fragment geometry identical to R12 (proven): warp w -> edges (w>>1)*16,
// cols (w&1)*64.
// ---------------------------------------------------------------------------
#define RT_THREADS 256
#define RT_TILE 64
#define ASTR 80
#define TSTR 136
#define RB_HI 0
#define RB_LO 8704
#define RA_HI 17408              // 64*80 = 5120
#define RA_LO 22528
#define RRAW  27648              // 2 x 8192
#define RXWG  44032              // 64*512 = 32768
#define RTACC 76800              // 64*136*4 = 34816
#define RSS   111616             // 2 x 256
#define RDS   112128             // 2 x 256
#define RT_SMEM 112640

__global__ __launch_bounds__(RT_THREADS, 2)
void rel_tc_kernel(const float* __restrict__ XW,
                   const float* __restrict__ Xe,
                   const int* __restrict__ src,
                   const int* __restrict__ dst,
                   const float* __restrict__ We,
                   float* __restrict__ out,
                   int E)
{
    extern __shared__ char smem[];
    const uint32_t sbase = smem_u32(smem);
    float* Tacc = (float*)(smem + RTACC);
    const float* XWg = (const float*)(smem + RXWG);

    const int tid  = threadIdx.x;
    const int warp = tid >> 5;
    const int lane = tid & 31;
    const int r0 = (warp >> 1) * 16;
    const int n0 = (warp & 1) * 64;

    // Stage B = We (32 x 128) bf16 hi/lo once per block.
    #pragma unroll
    for (int j = 0; j < 4; j++) {
        int idx = tid + j * RT_THREADS;     // 1024 float4 chunks
        int row = idx >> 5, c4 = idx & 31;
        uint2 hi, lo;
        cvt_hi_lo(((const float4*)We)[row * 32 + c4], hi, lo);
        *(uint2*)(smem + RB_HI + row * XSTRIDE + c4 * 8) = hi;
        *(uint2*)(smem + RB_LO + row * XSTRIDE + c4 * 8) = lo;
    }

    const uint32_t a_off = (uint32_t)((r0 + (lane & 15)) * ASTR + (lane >> 4) * 16);
    const int bg = lane >> 3;
    const uint32_t b_off = (uint32_t)(((lane & 7) + (bg & 1) * 8) * XSTRIDE
                                      + (n0 + (bg >> 1) * 8) * 2);

    const int ntiles = (E + RT_TILE - 1) / RT_TILE;
    const int G = gridDim.x;

    auto issue_A = [&](int tt, int buf) {
        int e0 = tt * RT_TILE;
        uint32_t rb = sbase + RRAW + buf * 8192;
        #pragma unroll
        for (int j = 0; j < 2; j++) {
            int idx = tid + j * RT_THREADS;     // 512 chunks: edge = idx>>3
            int e = e0 + (idx >> 3);
            int ok = (e < E);
            const float* g = Xe + (size_t)(ok ? e : 0) * 32 + (idx & 7) * 4;
            CPA16(rb + idx * 16, g, ok ? 16 : 0);
        }
        if (tid < RT_TILE) {
            int e = e0 + tid;
            int ok = (e < E);
            CPA4(sbase + RSS + buf * 256 + tid * 4, src + (ok ? e : 0), ok ? 4 : 0);
        } else if (tid < 2 * RT_TILE) {
            int e = e0 + tid - RT_TILE;
            int ok = (e < E);
            CPA4(sbase + RDS + buf * 256 + (tid - RT_TILE) * 4,
                 dst + (ok ? e : 0), ok ? 4 : 0);
        }
        CPA_COMMIT();
    };

    auto issue_B = [&](int buf) {
        const int* SsB = (const int*)(smem + RSS + buf * 256);
        #pragma unroll
        for (int j = 0; j < 8; j++) {
            int idx = tid + j * RT_THREADS;     // 2048 chunks: edge = idx>>5
            int el = idx >> 5, c = idx & 31;
            int s = SsB[el];
            const float* g = XW + (size_t)s * 128 + c * 4;
            CPA16(sbase + RXWG + idx * 16, g, 16);
        }
        CPA_COMMIT();
    };

    int t = blockIdx.x;
    int buf = 0;
    if (t < ntiles) issue_A(t, 0);
    __syncthreads();            // We staged

    for (; t < ntiles; t += G) {
        const int e0 = t * RT_TILE;
        const float4* rawv = (const float4*)(smem + RRAW + buf * 8192);
        const int* Ds = (const int*)(smem + RDS + buf * 256);

        CPA_WAIT0();            // A(t) landed
        __syncthreads();

        // raw Xe -> A hi/lo
        #pragma unroll
        for (int j = 0; j < 2; j++) {
            int idx = tid + j * RT_THREADS;
            int row = idx >> 3, c4 = idx & 7;
            uint2 hi, lo;
            cvt_hi_lo(rawv[idx], hi, lo);
            *(uint2*)(smem + RA_HI + row * ASTR + c4 * 8) = hi;
            *(uint2*)(smem + RA_LO + row * ASTR + c4 * 8) = lo;
        }
        __syncthreads();

        issue_B(buf);                                   // XW gather (tile t)
        if (t + G < ntiles) issue_A(t + G, buf ^ 1);    // next raw+idx
        else CPA_COMMIT();                              // group-count align

        float acc[8][4];
        #pragma unroll
        for (int i = 0; i < 8; i++)
            #pragma unroll
            for (int j = 0; j < 4; j++) acc[i][j] = 0.f;

        #pragma unroll
        for (int k0 = 0; k0 < 32; k0 += 16) {
            uint32_t ah[4], al[4];
            uint32_t aaddr = sbase + RA_HI + a_off + k0 * 2;
            LDSM4(ah, aaddr);
            LDSM4(al, aaddr + (RA_LO - RA_HI));
            #pragma unroll
            for (int c = 0; c < 4; c++) {
                uint32_t bh[4], bl[4];
                uint32_t baddr = sbase + RB_HI + b_off + k0 * XSTRIDE + c * 32;
                LDSM4T(bh, baddr);
                LDSM4T(bl, baddr + (RB_LO - RB_HI));
                MMA16816(acc[2 * c],     ah, bh[0], bh[1]);
                MMA16816(acc[2 * c + 1], ah, bh[2], bh[3]);
                MMA16816(acc[2 * c],     ah, bl[0], bl[1]);
                MMA16816(acc[2 * c + 1], ah, bl[2], bl[3]);
                MMA16816(acc[2 * c],     al, bh[0], bh[1]);
                MMA16816(acc[2 * c + 1], al, bh[2], bh[3]);
            }
        }

        // Fragments -> Tacc (row = edge-in-tile).
        {
            const int era = r0 + (lane >> 2);
            #pragma unroll
            for (int c8 = 0; c8 < 8; c8++) {
                int col = n0 + c8 * 8 + 2 * (lane & 3);
                *(float2*)(Tacc + era * TSTR + col) =
                    make_float2(acc[c8][0], acc[c8][1]);
                *(float2*)(Tacc + (era + 8) * TSTR + col) =
                    make_float2(acc[c8][2], acc[c8][3]);
            }
        }

        CPA_WAIT1();            // B(t) done; A(t+G) still in flight
        __syncthreads();

        // Coalesced epilogue: warp owns 8 edges.
        #pragma unroll
        for (int i = 0; i < 8; i++) {
            int el = warp * 8 + i;
            int e = e0 + el;
            if (e < E) {
                int d = Ds[el];
                float4 v = *(float4*)(Tacc + el * TSTR + 4 * lane);
                float4 g = *(const float4*)(XWg + el * 128 + 4 * lane);
                v.x = fmaxf(v.x + g.x, 0.f);
                v.y = fmaxf(v.y + g.y, 0.f);
                v.z = fmaxf(v.z + g.z, 0.f);
                v.w = fmaxf(v.w + g.w, 0.f);
                red_add_v4(out + (size_t)d * 128 + 4 * lane, v);
            }
        }

        buf ^= 1;
    }
}

// ---------------------------------------------------------------------------
// kernel_launch (metadata order unchanged)
// ---------------------------------------------------------------------------
extern "C" void kernel_launch(void* const* d_in, const int* in_sizes, int n_in,
                              void* d_out, int out_size)
{
    const float* X_user   = (const float*)d_in[0];
    const float* X_item   = (const float*)d_in[1];
    const float* Xe_ui    = (const float*)d_in[2];
    const float* Xe_iu    = (const float*)d_in[3];
    const float* W_src_ui = (const float*)d_in[4];
    const float* W_edge_ui= (const float*)d_in[5];
    const float* b_ui     = (const float*)d_in[6];
    const float* W_src_iu = (const float*)d_in[7];
    const float* W_edge_iu= (const float*)d_in[8];
    const float* b_iu     = (const float*)d_in[9];
    const float* Wl_user  = (const float*)d_in[10];
    const float* bl_user  = (const float*)d_in[11];
    const float* Wl_item  = (const float*)d_in[12];
    const float* bl_item  = (const float*)d_in[13];
    const int*   src_ui   = (const int*)d_in[14];
    const int*   dst_ui   = (const int*)d_in[15];
    const int*   src_iu   = (const int*)d_in[16];
    const int*   dst_iu   = (const int*)d_in[17];

    const int n_user = in_sizes[0] / D_IN;
    const int n_item = in_sizes[1] / D_IN;
    const int E      = in_sizes[14];

    float* H_user = (float*)d_out;
    float* H_item = (float*)d_out + (size_t)n_user * D_OUT;

    void* p_xwu = nullptr; void* p_xwi = nullptr;
    cudaGetSymbolAddress(&p_xwu, g_xwu);
    cudaGetSymbolAddress(&p_xwi, g_xwi);
    float* xwu = (float*)p_xwu;
    float* xwi = (float*)p_xwi;

    cudaFuncSetAttribute(node_tc_kernel,
                         cudaFuncAttributeMaxDynamicSharedMemorySize,
                         NT_SMEM);
    cudaFuncSetAttribute(rel_tc_kernel,
                         cudaFuncAttributeMaxDynamicSharedMemorySize,
                         RT_SMEM);

    node_tc_kernel<<<148, NT_THREADS, NT_SMEM>>>(
        X_user, X_item,
        W_src_ui, b_ui, xwu,
        Wl_user, bl_user, H_user,
        W_src_iu, b_iu, xwi,
        Wl_item, bl_item, H_item,
        n_user, n_item);

    // Sequential relations, 2 blocks/SM each.
    rel_tc_kernel<<<296, RT_THREADS, RT_SMEM>>>(
        xwu, Xe_ui, src_ui, dst_ui, W_edge_ui, H_item, E);
    rel_tc_kernel<<<296, RT_THREADS, RT_SMEM>>>(
        xwi, Xe_iu, src_iu, dst_iu, W_edge_iu, H_user, E);
}